// round 8
// baseline (speedup 1.0000x reference)
#include <cuda_runtime.h>
#include <math.h>
#include <stdint.h>

// Problem constants
#define BB 2
#define LL 1024
#define EE 1024
#define HH 16
#define DD 64
#define NCH 16
#define CHK 64
#define ST_STRIDE 8320
#define ROWS (BB*LL)    // 2048

// GEMM smem (tf32 bits), double buffered: A [m][k] pitch 36, B [k][n] pitch 136
#define APITCH 36
#define BPITCH 136
#define STAGE_WORDS (128 * APITCH + 32 * BPITCH)   // 8960
#define GEMM_SMEM_BYTES (2 * STAGE_WORDS * 4)      // 71680

// Scratch (device globals; no allocs allowed)
__device__ float g_xn[ROWS * EE];
__device__ float g_qkv[ROWS * 3 * EE];
__device__ float g_attn[ROWS * EE];
__device__ float g_h[ROWS * EE];
__device__ float g_mid[ROWS * 4 * EE];
__device__ float g_state[BB * HH * NCH * ST_STRIDE];

// ---------------------------------------------------------------------------
// helpers
// ---------------------------------------------------------------------------
__device__ __forceinline__ uint32_t f2tf32(float f) {
    uint32_t r;
    asm("cvt.rna.tf32.f32 %0, %1;" : "=r"(r) : "f"(f));
    return r;
}
__device__ __forceinline__ float tf32f(float f) {
    return __uint_as_float(f2tf32(f));
}

__device__ __forceinline__ void mma_tf32(float* c, const uint32_t* a,
                                         uint32_t b0, uint32_t b1) {
    asm volatile(
        "mma.sync.aligned.m16n8k8.row.col.f32.tf32.tf32.f32 "
        "{%0,%1,%2,%3}, {%4,%5,%6,%7}, {%8,%9}, {%0,%1,%2,%3};"
        : "+f"(c[0]), "+f"(c[1]), "+f"(c[2]), "+f"(c[3])
        : "r"(a[0]), "r"(a[1]), "r"(a[2]), "r"(a[3]),
          "r"(b0), "r"(b1));
}

__device__ __forceinline__ void ldsm_x4(uint32_t* d, uint32_t saddr) {
    asm volatile("ldmatrix.sync.aligned.m8n8.x4.shared.b16 {%0,%1,%2,%3}, [%4];"
                 : "=r"(d[0]), "=r"(d[1]), "=r"(d[2]), "=r"(d[3])
                 : "r"(saddr));
}

// ---------------------------------------------------------------------------
// TF32 mma.sync GEMM (round-4 skeleton):
//  - LDG->reg->STS double buffer (no cp.async), 1 sync per tile
//  - A activations are PRE-CONVERTED tf32 bits (producers emit them):
//    A STS is a plain float4 store. W converted at STS (16 cvt/thr/tile).
//  - A fragments via ldmatrix x4 (b32 reinterp), B via conflict-free LDS.
//  - __launch_bounds__(256,2): cap regs at 128 -> 2 CTAs/SM.
// C[M,N] = A[M,K] @ W[K,N] + bias (+gelu | +res)
// 128x128 tile, BK=32, 8 warps (2x4), warp tile 64x32.
// epi: 0=bias 1=bias+gelu 2=bias+res. ocvt: emit tf32-bit output.
// ---------------------------------------------------------------------------
__global__ void __launch_bounds__(256, 2)
tgemm_kernel(const float* __restrict__ A, const float* __restrict__ W,
             const float* __restrict__ bias, const float* __restrict__ res,
             float* __restrict__ C, int M, int N, int K, int epi, int ocvt) {
    extern __shared__ uint32_t smu[];
    uint32_t sbase = (uint32_t)__cvta_generic_to_shared(smu);

    int tid = threadIdx.x;
    int bx = blockIdx.x;   // N tile
    int by = blockIdx.y;   // M tile
    int warp = tid >> 5;
    int lane = tid & 31;
    int wm = warp >> 2;    // 0..1
    int wn = warp & 3;     // 0..3
    int g  = lane >> 2;    // 0..7
    int tg = lane & 3;     // 0..3

    float acc[4][4][4];
    #pragma unroll
    for (int mi = 0; mi < 4; mi++)
        #pragma unroll
        for (int ni = 0; ni < 4; ni++)
            #pragma unroll
            for (int r = 0; r < 4; r++) acc[mi][ni][r] = 0.f;

    // A copy: row m = tid>>1 (0..127), k base = (tid&1)*16, 4 x float4
    int am = tid >> 1;
    int ak = (tid & 1) * 16;
    const float* Ag = A + (size_t)(by * 128 + am) * K + ak;
    // W copy: row k = tid>>3 (0..31), n base = (tid&7)*16, 4 x float4
    int bk = tid >> 3;
    int bn = (tid & 7) * 16;
    const float* Wg = W + (size_t)bk * N + bx * 128 + bn;

    // ldmatrix lane offset for A fragments (words)
    int sel = lane >> 3;
    int rr  = lane & 7;
    int aLaneOff = ((sel & 1) * 8 + rr) * APITCH + (sel >> 1) * 4;

    int m0base = wm * 64;
    int n0base = wn * 32;
    int nT = K >> 5;

    float4 aReg[4], bReg[4];
    auto ldg = [&](int t) {
        const float* Asrc = Ag + t * 32;
        const float* Wsrc = Wg + (size_t)t * 32 * N;
        #pragma unroll
        for (int i = 0; i < 4; i++) aReg[i] = *(const float4*)(Asrc + i * 4);
        #pragma unroll
        for (int i = 0; i < 4; i++) bReg[i] = *(const float4*)(Wsrc + i * 4);
    };
    auto sts = [&](int buf) {
        float* sA = (float*)smu + buf * STAGE_WORDS;
        uint32_t* sB = (uint32_t*)sA + 128 * APITCH;
        #pragma unroll
        for (int i = 0; i < 4; i++)
            *(float4*)&sA[am * APITCH + ak + i * 4] = aReg[i];   // already tf32 bits
        #pragma unroll
        for (int i = 0; i < 4; i++) {
            uint4 u;
            u.x = f2tf32(bReg[i].x); u.y = f2tf32(bReg[i].y);
            u.z = f2tf32(bReg[i].z); u.w = f2tf32(bReg[i].w);
            *(uint4*)&sB[bk * BPITCH + bn + i * 4] = u;
        }
    };

    // prologue
    ldg(0);
    sts(0);
    ldg(1);
    __syncthreads();

    for (int t = 0; t < nT; t++) {
        if (t + 1 < nT) sts((t + 1) & 1);
        if (t + 2 < nT) ldg(t + 2);

        uint32_t sA = sbase + (uint32_t)((t & 1) * STAGE_WORDS) * 4u;
        const uint32_t* sB = smu + (t & 1) * STAGE_WORDS + 128 * APITCH;

        #pragma unroll
        for (int ks = 0; ks < 4; ks++) {
            int k0 = ks * 8;
            uint32_t af[4][4];
            #pragma unroll
            for (int mi = 0; mi < 4; mi++)
                ldsm_x4(af[mi], sA + 4u * (uint32_t)((m0base + mi * 16) * APITCH + k0 + aLaneOff));
            uint32_t bf[4][2];
            #pragma unroll
            for (int ni = 0; ni < 4; ni++) {
                int idx = (k0 + tg) * BPITCH + n0base + ni * 8 + g;
                bf[ni][0] = sB[idx];
                bf[ni][1] = sB[idx + 4 * BPITCH];
            }
            #pragma unroll
            for (int mi = 0; mi < 4; mi++)
                #pragma unroll
                for (int ni = 0; ni < 4; ni++)
                    mma_tf32(acc[mi][ni], af[mi], bf[ni][0], bf[ni][1]);
        }
        __syncthreads();
    }

    // Epilogue. c0:(g, 2tg) c1:(g, 2tg+1) c2:(g+8, 2tg) c3:(g+8, 2tg+1)
    #pragma unroll
    for (int mi = 0; mi < 4; mi++) {
        #pragma unroll
        for (int ni = 0; ni < 4; ni++) {
            int col = bx * 128 + wn * 32 + ni * 8 + tg * 2;
            float b0 = bias[col], b1 = bias[col + 1];
            #pragma unroll
            for (int half = 0; half < 2; half++) {
                int orow = by * 128 + wm * 64 + mi * 16 + g + half * 8;
                size_t off = (size_t)orow * N + col;
                float v0 = acc[mi][ni][half * 2 + 0] + b0;
                float v1 = acc[mi][ni][half * 2 + 1] + b1;
                if (epi == 1) {
                    float u0 = v0 * (0.7978845608028654f + 0.035677408136300125f * v0 * v0);
                    float u1 = v1 * (0.7978845608028654f + 0.035677408136300125f * v1 * v1);
                    v0 = 0.5f * v0 * (1.f + tanhf(u0));
                    v1 = 0.5f * v1 * (1.f + tanhf(u1));
                } else if (epi == 2) {
                    v0 += res[off];
                    v1 += res[off + 1];
                }
                if (ocvt) { v0 = tf32f(v0); v1 = tf32f(v1); }
                *(float2*)(C + off) = make_float2(v0, v1);
            }
        }
    }
}

// ---------------------------------------------------------------------------
// RMSNorm (optionally emits tf32-bit output for GEMM consumption)
// ---------------------------------------------------------------------------
__global__ void rmsnorm_kernel(const float* __restrict__ x,
                               const float* __restrict__ w,
                               float* __restrict__ out, int cvt) {
    int row = blockIdx.x;
    int tid = threadIdx.x;
    const float4* xr = (const float4*)(x + (size_t)row * EE);
    float4 v = xr[tid];
    float ss = v.x*v.x + v.y*v.y + v.z*v.z + v.w*v.w;
    #pragma unroll
    for (int o = 16; o; o >>= 1) ss += __shfl_xor_sync(0xffffffffu, ss, o);
    __shared__ float red[8];
    if ((tid & 31) == 0) red[tid >> 5] = ss;
    __syncthreads();
    float tot = 0.f;
    #pragma unroll
    for (int i = 0; i < 8; i++) tot += red[i];
    float scale = rsqrtf(tot * (1.0f / (float)EE) + 1e-6f);
    float4 wv = ((const float4*)w)[tid];
    float4 o;
    o.x = v.x * scale * wv.x;
    o.y = v.y * scale * wv.y;
    o.z = v.z * scale * wv.z;
    o.w = v.w * scale * wv.w;
    if (cvt) {
        o.x = tf32f(o.x); o.y = tf32f(o.y); o.z = tf32f(o.z); o.w = tf32f(o.w);
    }
    ((float4*)(out + (size_t)row * EE))[tid] = o;
}

// ---------------------------------------------------------------------------
// Attention pass A: per-chunk state sums.
// ---------------------------------------------------------------------------
__global__ void __launch_bounds__(256)
attn_chunk_state(const float* __restrict__ qkv, float* __restrict__ state) {
    int blk = blockIdx.x;
    int c = blk % NCH;
    int bh = blk / NCH;
    int b = bh / HH, h = bh % HH;

    __shared__ float sk[CHK][DD + 1];
    __shared__ float sv[CHK][DD + 1];
    __shared__ float cw[CHK], sw[CHK];

    int tid = threadIdx.x;
    for (int idx = tid; idx < CHK * 16; idx += 256) {
        int j = idx >> 4;
        int dd = (idx & 15) << 2;
        int l = c * CHK + j;
        const float* base = qkv + (size_t)(b * LL + l) * (3 * EE) + h * DD;
        float4 kv = *(const float4*)(base + EE + dd);
        float4 vv = *(const float4*)(base + 2 * EE + dd);
        sk[j][dd + 0] = fmaxf(kv.x, 0.f);
        sk[j][dd + 1] = fmaxf(kv.y, 0.f);
        sk[j][dd + 2] = fmaxf(kv.z, 0.f);
        sk[j][dd + 3] = fmaxf(kv.w, 0.f);
        sv[j][dd + 0] = vv.x;
        sv[j][dd + 1] = vv.y;
        sv[j][dd + 2] = vv.z;
        sv[j][dd + 3] = vv.w;
    }
    if (tid < CHK) {
        float ang = 1.5707963267948966f * (float)(c * CHK + tid) / (float)LL;
        cw[tid] = cosf(ang);
        sw[tid] = sinf(ang);
    }
    __syncthreads();

    int e  = tid & 63;
    int d0 = (tid >> 6) * 16;
    float accC[16], accS[16];
    #pragma unroll
    for (int r = 0; r < 16; r++) { accC[r] = 0.f; accS[r] = 0.f; }

    for (int j = 0; j < CHK; j++) {
        float ve = sv[j][e];
        float t1 = ve * cw[j];
        float t2 = ve * sw[j];
        #pragma unroll
        for (int r = 0; r < 16; r++) {
            float kd = sk[j][d0 + r];
            accC[r] = fmaf(kd, t1, accC[r]);
            accS[r] = fmaf(kd, t2, accS[r]);
        }
    }

    float* st = state + ((size_t)bh * NCH + c) * ST_STRIDE;
    #pragma unroll
    for (int r = 0; r < 16; r++) {
        st[(d0 + r) * 64 + e]        = accC[r];
        st[4096 + (d0 + r) * 64 + e] = accS[r];
    }
    if (tid < DD) {
        float zc = 0.f, zs = 0.f;
        for (int j = 0; j < CHK; j++) {
            float kd = sk[j][tid];
            zc = fmaf(kd, cw[j], zc);
            zs = fmaf(kd, sw[j], zs);
        }
        st[8192 + tid] = zc;
        st[8256 + tid] = zs;
    }
}

// ---------------------------------------------------------------------------
// Attention pass B: exclusive prefix over chunks (in-place).
// ---------------------------------------------------------------------------
__global__ void attn_prefix(float* __restrict__ state) {
    int bh  = blockIdx.y;
    int idx = blockIdx.x * 256 + threadIdx.x;
    if (idx >= ST_STRIDE) return;
    float* p = state + (size_t)bh * NCH * ST_STRIDE + idx;
    float vals[NCH];
    #pragma unroll
    for (int cc = 0; cc < NCH; cc++) vals[cc] = p[(size_t)cc * ST_STRIDE];
    float run = 0.f;
    #pragma unroll
    for (int cc = 0; cc < NCH; cc++) {
        p[(size_t)cc * ST_STRIDE] = run;
        run += vals[cc];
    }
}

// ---------------------------------------------------------------------------
// Attention pass C: per-chunk output (emits tf32 bits for out-proj GEMM).
// ---------------------------------------------------------------------------
#define ATTN_SMEM_FLOATS (6 * 64 * 65 + 64 + 64 + 64 + 64 + 256 + 64)
#define ATTN_SMEM_BYTES (ATTN_SMEM_FLOATS * 4)

__global__ void __launch_bounds__(256)
attn_out_kernel(const float* __restrict__ qkv, const float* __restrict__ state,
                float* __restrict__ out) {
    extern __shared__ float smf[];
    float* sq = smf;
    float* sk = sq + 4160;
    float* sv = sk + 4160;
    float* Sc = sv + 4160;
    float* Ss = Sc + 4160;
    float* AS = Ss + 4160;
    float* cw = AS + 4160;
    float* sw = cw + 64;
    float* Zc = sw + 64;
    float* Zs = Zc + 64;
    float* normp = Zs + 64;
    float* normF = normp + 256;

    int blk = blockIdx.x;
    int c = blk % NCH;
    int bh = blk / NCH;
    int b = bh / HH, h = bh % HH;
    int tid = threadIdx.x;

    const float* st = state + ((size_t)bh * NCH + c) * ST_STRIDE;

    for (int idx = tid; idx < CHK * 16; idx += 256) {
        int j = idx >> 4;
        int dd = (idx & 15) << 2;
        int l = c * CHK + j;
        const float* base = qkv + (size_t)(b * LL + l) * (3 * EE) + h * DD;
        float4 qv = *(const float4*)(base + dd);
        float4 kv = *(const float4*)(base + EE + dd);
        float4 vv = *(const float4*)(base + 2 * EE + dd);
        int ro = j * 65 + dd;
        sq[ro + 0] = fmaxf(qv.x, 0.f); sq[ro + 1] = fmaxf(qv.y, 0.f);
        sq[ro + 2] = fmaxf(qv.z, 0.f); sq[ro + 3] = fmaxf(qv.w, 0.f);
        sk[ro + 0] = fmaxf(kv.x, 0.f); sk[ro + 1] = fmaxf(kv.y, 0.f);
        sk[ro + 2] = fmaxf(kv.z, 0.f); sk[ro + 3] = fmaxf(kv.w, 0.f);
        sv[ro + 0] = vv.x; sv[ro + 1] = vv.y; sv[ro + 2] = vv.z; sv[ro + 3] = vv.w;
        int flat = idx << 2;
        int d = flat >> 6, e = flat & 63;
        float4 scv = *(const float4*)(st + flat);
        float4 ssv = *(const float4*)(st + 4096 + flat);
        int so = d * 65 + e;
        Sc[so + 0] = scv.x; Sc[so + 1] = scv.y; Sc[so + 2] = scv.z; Sc[so + 3] = scv.w;
        Ss[so + 0] = ssv.x; Ss[so + 1] = ssv.y; Ss[so + 2] = ssv.z; Ss[so + 3] = ssv.w;
    }
    if (tid < CHK) {
        float ang = 1.5707963267948966f * (float)(c * CHK + tid) / (float)LL;
        cw[tid] = cosf(ang);
        sw[tid] = sinf(ang);
        Zc[tid] = st[8192 + tid];
        Zs[tid] = st[8256 + tid];
    }
    __syncthreads();

    {
        int jc = tid >> 6;
        int i  = tid & 63;
        float acc[16];
        #pragma unroll
        for (int r = 0; r < 16; r++) acc[r] = 0.f;
        for (int d = 0; d < DD; d++) {
            float qv = sq[i * 65 + d];
            #pragma unroll
            for (int r = 0; r < 16; r++)
                acc[r] = fmaf(qv, sk[(jc * 16 + r) * 65 + d], acc[r]);
        }
        float cwi = cw[i], swi = sw[i];
        float rsum = 0.f;
        #pragma unroll
        for (int r = 0; r < 16; r++) {
            int j = jc * 16 + r;
            float wgt = (j <= i) ? (cwi * cw[j] + swi * sw[j]) : 0.f;
            float a = acc[r] * wgt;
            AS[i * 65 + j] = a;
            rsum += a;
        }
        normp[jc * 64 + i] = rsum;
    }
    __syncthreads();

    if (tid < 64) {
        int i = tid;
        float n = normp[i] + normp[64 + i] + normp[128 + i] + normp[192 + i];
        float dc = 0.f, ds = 0.f;
        for (int d = 0; d < DD; d++) {
            float qv = sq[i * 65 + d];
            dc = fmaf(qv, Zc[d], dc);
            ds = fmaf(qv, Zs[d], ds);
        }
        normF[i] = n + cw[i] * dc + sw[i] * ds;
    }

    int ec = tid >> 6;
    int i2 = tid & 63;
    int e0 = ec * 16;
    float accO[16], accC2[16], accS2[16];
    #pragma unroll
    for (int r = 0; r < 16; r++) { accO[r] = 0.f; accC2[r] = 0.f; accS2[r] = 0.f; }

    for (int j = 0; j < CHK; j++) {
        float av = AS[i2 * 65 + j];
        #pragma unroll
        for (int r = 0; r < 16; r++)
            accO[r] = fmaf(av, sv[j * 65 + e0 + r], accO[r]);
    }
    for (int d = 0; d < DD; d++) {
        float qv = sq[i2 * 65 + d];
        #pragma unroll
        for (int r = 0; r < 16; r++) {
            accC2[r] = fmaf(qv, Sc[d * 65 + e0 + r], accC2[r]);
            accS2[r] = fmaf(qv, Ss[d * 65 + e0 + r], accS2[r]);
        }
    }
    __syncthreads();

    float nrm = normF[i2] + 1e-6f;
    float inv = 1.0f / nrm;
    float cwi = cw[i2], swi = sw[i2];
    int lg = c * CHK + i2;
    float* op = out + (size_t)(b * LL + lg) * EE + h * DD + e0;
    #pragma unroll
    for (int r4 = 0; r4 < 4; r4++) {
        float4 o;
        o.x = tf32f((accO[r4*4+0] + cwi*accC2[r4*4+0] + swi*accS2[r4*4+0]) * inv);
        o.y = tf32f((accO[r4*4+1] + cwi*accC2[r4*4+1] + swi*accS2[r4*4+1]) * inv);
        o.z = tf32f((accO[r4*4+2] + cwi*accC2[r4*4+2] + swi*accS2[r4*4+2]) * inv);
        o.w = tf32f((accO[r4*4+3] + cwi*accC2[r4*4+3] + swi*accS2[r4*4+3]) * inv);
        *(float4*)(op + r4 * 4) = o;
    }
}

// ---------------------------------------------------------------------------
// launch
// ---------------------------------------------------------------------------
extern "C" void kernel_launch(void* const* d_in, const int* in_sizes, int n_in,
                              void* d_out, int out_size) {
    const float* x       = (const float*)d_in[0];
    const float* qkv_w   = (const float*)d_in[1];
    const float* qkv_b   = (const float*)d_in[2];
    const float* out_w   = (const float*)d_in[3];
    const float* out_b   = (const float*)d_in[4];
    const float* norm1_w = (const float*)d_in[5];
    const float* norm2_w = (const float*)d_in[6];
    const float* mlp_w1  = (const float*)d_in[7];
    const float* mlp_b1  = (const float*)d_in[8];
    const float* mlp_w2  = (const float*)d_in[9];
    const float* mlp_b2  = (const float*)d_in[10];
    float* out = (float*)d_out;

    float *xn, *qkv, *attn, *hbuf, *mid, *state;
    cudaGetSymbolAddress((void**)&xn, g_xn);
    cudaGetSymbolAddress((void**)&qkv, g_qkv);
    cudaGetSymbolAddress((void**)&attn, g_attn);
    cudaGetSymbolAddress((void**)&hbuf, g_h);
    cudaGetSymbolAddress((void**)&mid, g_mid);
    cudaGetSymbolAddress((void**)&state, g_state);

    cudaFuncSetAttribute(attn_out_kernel,
                         cudaFuncAttributeMaxDynamicSharedMemorySize,
                         ATTN_SMEM_BYTES);
    cudaFuncSetAttribute(tgemm_kernel,
                         cudaFuncAttributeMaxDynamicSharedMemorySize,
                         GEMM_SMEM_BYTES);

    // 1. xn = tf32(rmsnorm(x, norm1_w))
    rmsnorm_kernel<<<ROWS, 256>>>(x, norm1_w, xn, 1);
    // 2. qkv = xn @ qkv_w + qkv_b (fp32, consumed by attention)
    tgemm_kernel<<<dim3(3 * EE / 128, ROWS / 128), 256, GEMM_SMEM_BYTES>>>(
        xn, qkv_w, qkv_b, nullptr, qkv, ROWS, 3 * EE, EE, 0, 0);
    // 3-5. cosformer attention (chunked); attn emitted as tf32 bits
    attn_chunk_state<<<BB * HH * NCH, 256>>>(qkv, state);
    attn_prefix<<<dim3((ST_STRIDE + 255) / 256, BB * HH), 256>>>(state);
    attn_out_kernel<<<BB * HH * NCH, 256, ATTN_SMEM_BYTES>>>(qkv, state, attn);
    // 6. h = attn @ out_w + out_b + x (fp32: rmsnorm + residual consumer)
    tgemm_kernel<<<dim3(EE / 128, ROWS / 128), 256, GEMM_SMEM_BYTES>>>(
        attn, out_w, out_b, x, hbuf, ROWS, EE, EE, 2, 0);
    // 7. xn = tf32(rmsnorm(h, norm2_w))
    rmsnorm_kernel<<<ROWS, 256>>>(hbuf, norm2_w, xn, 1);
    // 8. mid = tf32(gelu(xn @ mlp_w1 + mlp_b1))
    tgemm_kernel<<<dim3(4 * EE / 128, ROWS / 128), 256, GEMM_SMEM_BYTES>>>(
        xn, mlp_w1, mlp_b1, nullptr, mid, ROWS, 4 * EE, EE, 1, 1);
    // 9. out = mid @ mlp_w2 + mlp_b2 + h (fp32 final)
    tgemm_kernel<<<dim3(EE / 128, ROWS / 128), 256, GEMM_SMEM_BYTES>>>(
        mid, mlp_w2, mlp_b2, hbuf, out, ROWS, EE, 4 * EE, 2, 0);
}

// round 9
// speedup vs baseline: 1.3097x; 1.3097x over previous
#include <cuda_runtime.h>
#include <math.h>
#include <stdint.h>

// Problem constants
#define BB 2
#define LL 1024
#define EE 1024
#define HH 16
#define DD 64
#define NCH 16
#define CHK 64
#define ST_STRIDE 8320
#define ROWS (BB*LL)    // 2048

// GEMM smem (tf32 bits), double buffered: A [m][k] pitch 36, B [k][n] pitch 136
#define APITCH 36
#define BPITCH 136
#define STAGE_WORDS (128 * APITCH + 32 * BPITCH)   // 8960
#define GEMM_SMEM_BYTES (2 * STAGE_WORDS * 4)      // 71680

// Scratch (device globals; no allocs allowed)
__device__ float g_xn[ROWS * EE];
__device__ float g_qkv[ROWS * 3 * EE];
__device__ float g_attn[ROWS * EE];
__device__ float g_h[ROWS * EE];
__device__ float g_mid[ROWS * 4 * EE];
__device__ float g_state[BB * HH * NCH * ST_STRIDE];

// ---------------------------------------------------------------------------
// helpers
// ---------------------------------------------------------------------------
__device__ __forceinline__ uint32_t f2tf32(float f) {
    uint32_t r;
    asm("cvt.rna.tf32.f32 %0, %1;" : "=r"(r) : "f"(f));
    return r;
}
__device__ __forceinline__ float tf32f(float f) {
    return __uint_as_float(f2tf32(f));
}

__device__ __forceinline__ void mma_tf32(float* c, const uint32_t* a,
                                         uint32_t b0, uint32_t b1) {
    asm volatile(
        "mma.sync.aligned.m16n8k8.row.col.f32.tf32.tf32.f32 "
        "{%0,%1,%2,%3}, {%4,%5,%6,%7}, {%8,%9}, {%0,%1,%2,%3};"
        : "+f"(c[0]), "+f"(c[1]), "+f"(c[2]), "+f"(c[3])
        : "r"(a[0]), "r"(a[1]), "r"(a[2]), "r"(a[3]),
          "r"(b0), "r"(b1));
}

__device__ __forceinline__ void ldsm_x4(uint32_t* d, uint32_t saddr) {
    asm volatile("ldmatrix.sync.aligned.m8n8.x4.shared.b16 {%0,%1,%2,%3}, [%4];"
                 : "=r"(d[0]), "=r"(d[1]), "=r"(d[2]), "=r"(d[3])
                 : "r"(saddr));
}

// ---------------------------------------------------------------------------
// TF32 mma.sync GEMM, 512 threads / 16 warps (4x4), warp tile 32x32:
//  - LDG->reg->STS double buffer, 1 sync per tile (round-4 skeleton)
//  - 4 warps/SMSP hide ldmatrix->mma latency (~85 regs/thr, no cap/spills)
//  - A activations PRE-CONVERTED tf32 (plain STS); W cvt at STS (8/thr/tile)
//  - A frags via ldmatrix x4; B via conflict-free scalar LDS (pitch 136)
// C[M,N] = A[M,K] @ W[K,N] + bias (+gelu | +res)
// epi: 0=bias 1=bias+gelu 2=bias+res. ocvt: emit tf32-bit output.
// ---------------------------------------------------------------------------
__global__ void __launch_bounds__(512)
tgemm_kernel(const float* __restrict__ A, const float* __restrict__ W,
             const float* __restrict__ bias, const float* __restrict__ res,
             float* __restrict__ C, int M, int N, int K, int epi, int ocvt) {
    extern __shared__ uint32_t smu[];
    uint32_t sbase = (uint32_t)__cvta_generic_to_shared(smu);

    int tid = threadIdx.x;
    int bx = blockIdx.x;   // N tile
    int by = blockIdx.y;   // M tile
    int warp = tid >> 5;
    int lane = tid & 31;
    int wm = warp >> 2;    // 0..3 (M dir, 32 rows each)
    int wn = warp & 3;     // 0..3 (N dir, 32 cols each)
    int g  = lane >> 2;    // 0..7
    int tg = lane & 3;     // 0..3

    float acc[2][4][4];
    #pragma unroll
    for (int mi = 0; mi < 2; mi++)
        #pragma unroll
        for (int ni = 0; ni < 4; ni++)
            #pragma unroll
            for (int r = 0; r < 4; r++) acc[mi][ni][r] = 0.f;

    // A copy: row m = tid>>2 (0..127), k0 = (tid&3)*8; two float4 at k0, k0+4
    int am = tid >> 2;
    int ak = (tid & 3) * 8;
    const float* Ag = A + (size_t)(by * 128 + am) * K + ak;
    // W copy: row k = tid>>4 (0..31), n0 = (tid&15)*4; two float4 at n0, n0+64
    int bk = tid >> 4;
    int bn = (tid & 15) * 4;
    const float* Wg = W + (size_t)bk * N + bx * 128 + bn;

    // ldmatrix lane offset for A fragments (words)
    int sel = lane >> 3;
    int rr  = lane & 7;
    int aLaneOff = ((sel & 1) * 8 + rr) * APITCH + (sel >> 1) * 4;

    int m0base = wm * 32;
    int n0base = wn * 32;
    int nT = K >> 5;

    float4 aReg[2], bReg[2];
    auto ldg = [&](int t) {
        const float* Asrc = Ag + t * 32;
        const float* Wsrc = Wg + (size_t)t * 32 * N;
        aReg[0] = *(const float4*)(Asrc);
        aReg[1] = *(const float4*)(Asrc + 4);
        bReg[0] = *(const float4*)(Wsrc);
        bReg[1] = *(const float4*)(Wsrc + 64);
    };
    auto sts = [&](int buf) {
        float* sA = (float*)smu + buf * STAGE_WORDS;
        uint32_t* sB = (uint32_t*)sA + 128 * APITCH;
        *(float4*)&sA[am * APITCH + ak]     = aReg[0];   // already tf32 bits
        *(float4*)&sA[am * APITCH + ak + 4] = aReg[1];
        #pragma unroll
        for (int i = 0; i < 2; i++) {
            uint4 u;
            u.x = f2tf32(bReg[i].x); u.y = f2tf32(bReg[i].y);
            u.z = f2tf32(bReg[i].z); u.w = f2tf32(bReg[i].w);
            *(uint4*)&sB[bk * BPITCH + bn + i * 64] = u;
        }
    };

    // prologue
    ldg(0);
    sts(0);
    ldg(1);
    __syncthreads();

    for (int t = 0; t < nT; t++) {
        if (t + 1 < nT) sts((t + 1) & 1);
        if (t + 2 < nT) ldg(t + 2);

        uint32_t sA = sbase + (uint32_t)((t & 1) * STAGE_WORDS) * 4u;
        const uint32_t* sB = smu + (t & 1) * STAGE_WORDS + 128 * APITCH;

        #pragma unroll
        for (int ks = 0; ks < 4; ks++) {
            int k0 = ks * 8;
            uint32_t af[2][4];
            #pragma unroll
            for (int mi = 0; mi < 2; mi++)
                ldsm_x4(af[mi], sA + 4u * (uint32_t)((m0base + mi * 16) * APITCH + k0 + aLaneOff));
            uint32_t bf[4][2];
            #pragma unroll
            for (int ni = 0; ni < 4; ni++) {
                int idx = (k0 + tg) * BPITCH + n0base + ni * 8 + g;
                bf[ni][0] = sB[idx];
                bf[ni][1] = sB[idx + 4 * BPITCH];
            }
            #pragma unroll
            for (int mi = 0; mi < 2; mi++)
                #pragma unroll
                for (int ni = 0; ni < 4; ni++)
                    mma_tf32(acc[mi][ni], af[mi], bf[ni][0], bf[ni][1]);
        }
        __syncthreads();
    }

    // Epilogue. c0:(g, 2tg) c1:(g, 2tg+1) c2:(g+8, 2tg) c3:(g+8, 2tg+1)
    #pragma unroll
    for (int mi = 0; mi < 2; mi++) {
        #pragma unroll
        for (int ni = 0; ni < 4; ni++) {
            int col = bx * 128 + wn * 32 + ni * 8 + tg * 2;
            float b0 = bias[col], b1 = bias[col + 1];
            #pragma unroll
            for (int half = 0; half < 2; half++) {
                int orow = by * 128 + wm * 32 + mi * 16 + g + half * 8;
                size_t off = (size_t)orow * N + col;
                float v0 = acc[mi][ni][half * 2 + 0] + b0;
                float v1 = acc[mi][ni][half * 2 + 1] + b1;
                if (epi == 1) {
                    float u0 = v0 * (0.7978845608028654f + 0.035677408136300125f * v0 * v0);
                    float u1 = v1 * (0.7978845608028654f + 0.035677408136300125f * v1 * v1);
                    v0 = 0.5f * v0 * (1.f + tanhf(u0));
                    v1 = 0.5f * v1 * (1.f + tanhf(u1));
                } else if (epi == 2) {
                    v0 += res[off];
                    v1 += res[off + 1];
                }
                if (ocvt) { v0 = tf32f(v0); v1 = tf32f(v1); }
                *(float2*)(C + off) = make_float2(v0, v1);
            }
        }
    }
}

// ---------------------------------------------------------------------------
// RMSNorm (optionally emits tf32-bit output for GEMM consumption)
// ---------------------------------------------------------------------------
__global__ void rmsnorm_kernel(const float* __restrict__ x,
                               const float* __restrict__ w,
                               float* __restrict__ out, int cvt) {
    int row = blockIdx.x;
    int tid = threadIdx.x;
    const float4* xr = (const float4*)(x + (size_t)row * EE);
    float4 v = xr[tid];
    float ss = v.x*v.x + v.y*v.y + v.z*v.z + v.w*v.w;
    #pragma unroll
    for (int o = 16; o; o >>= 1) ss += __shfl_xor_sync(0xffffffffu, ss, o);
    __shared__ float red[8];
    if ((tid & 31) == 0) red[tid >> 5] = ss;
    __syncthreads();
    float tot = 0.f;
    #pragma unroll
    for (int i = 0; i < 8; i++) tot += red[i];
    float scale = rsqrtf(tot * (1.0f / (float)EE) + 1e-6f);
    float4 wv = ((const float4*)w)[tid];
    float4 o;
    o.x = v.x * scale * wv.x;
    o.y = v.y * scale * wv.y;
    o.z = v.z * scale * wv.z;
    o.w = v.w * scale * wv.w;
    if (cvt) {
        o.x = tf32f(o.x); o.y = tf32f(o.y); o.z = tf32f(o.z); o.w = tf32f(o.w);
    }
    ((float4*)(out + (size_t)row * EE))[tid] = o;
}

// ---------------------------------------------------------------------------
// Attention pass A: per-chunk state sums.
// ---------------------------------------------------------------------------
__global__ void __launch_bounds__(256)
attn_chunk_state(const float* __restrict__ qkv, float* __restrict__ state) {
    int blk = blockIdx.x;
    int c = blk % NCH;
    int bh = blk / NCH;
    int b = bh / HH, h = bh % HH;

    __shared__ float sk[CHK][DD + 1];
    __shared__ float sv[CHK][DD + 1];
    __shared__ float cw[CHK], sw[CHK];

    int tid = threadIdx.x;
    for (int idx = tid; idx < CHK * 16; idx += 256) {
        int j = idx >> 4;
        int dd = (idx & 15) << 2;
        int l = c * CHK + j;
        const float* base = qkv + (size_t)(b * LL + l) * (3 * EE) + h * DD;
        float4 kv = *(const float4*)(base + EE + dd);
        float4 vv = *(const float4*)(base + 2 * EE + dd);
        sk[j][dd + 0] = fmaxf(kv.x, 0.f);
        sk[j][dd + 1] = fmaxf(kv.y, 0.f);
        sk[j][dd + 2] = fmaxf(kv.z, 0.f);
        sk[j][dd + 3] = fmaxf(kv.w, 0.f);
        sv[j][dd + 0] = vv.x;
        sv[j][dd + 1] = vv.y;
        sv[j][dd + 2] = vv.z;
        sv[j][dd + 3] = vv.w;
    }
    if (tid < CHK) {
        float ang = 1.5707963267948966f * (float)(c * CHK + tid) / (float)LL;
        cw[tid] = cosf(ang);
        sw[tid] = sinf(ang);
    }
    __syncthreads();

    int e  = tid & 63;
    int d0 = (tid >> 6) * 16;
    float accC[16], accS[16];
    #pragma unroll
    for (int r = 0; r < 16; r++) { accC[r] = 0.f; accS[r] = 0.f; }

    for (int j = 0; j < CHK; j++) {
        float ve = sv[j][e];
        float t1 = ve * cw[j];
        float t2 = ve * sw[j];
        #pragma unroll
        for (int r = 0; r < 16; r++) {
            float kd = sk[j][d0 + r];
            accC[r] = fmaf(kd, t1, accC[r]);
            accS[r] = fmaf(kd, t2, accS[r]);
        }
    }

    float* st = state + ((size_t)bh * NCH + c) * ST_STRIDE;
    #pragma unroll
    for (int r = 0; r < 16; r++) {
        st[(d0 + r) * 64 + e]        = accC[r];
        st[4096 + (d0 + r) * 64 + e] = accS[r];
    }
    if (tid < DD) {
        float zc = 0.f, zs = 0.f;
        for (int j = 0; j < CHK; j++) {
            float kd = sk[j][tid];
            zc = fmaf(kd, cw[j], zc);
            zs = fmaf(kd, sw[j], zs);
        }
        st[8192 + tid] = zc;
        st[8256 + tid] = zs;
    }
}

// ---------------------------------------------------------------------------
// Attention pass B: exclusive prefix over chunks (in-place).
// ---------------------------------------------------------------------------
__global__ void attn_prefix(float* __restrict__ state) {
    int bh  = blockIdx.y;
    int idx = blockIdx.x * 256 + threadIdx.x;
    if (idx >= ST_STRIDE) return;
    float* p = state + (size_t)bh * NCH * ST_STRIDE + idx;
    float vals[NCH];
    #pragma unroll
    for (int cc = 0; cc < NCH; cc++) vals[cc] = p[(size_t)cc * ST_STRIDE];
    float run = 0.f;
    #pragma unroll
    for (int cc = 0; cc < NCH; cc++) {
        p[(size_t)cc * ST_STRIDE] = run;
        run += vals[cc];
    }
}

// ---------------------------------------------------------------------------
// Attention pass C: per-chunk output (emits tf32 bits for out-proj GEMM).
// ---------------------------------------------------------------------------
#define ATTN_SMEM_FLOATS (6 * 64 * 65 + 64 + 64 + 64 + 64 + 256 + 64)
#define ATTN_SMEM_BYTES (ATTN_SMEM_FLOATS * 4)

__global__ void __launch_bounds__(256)
attn_out_kernel(const float* __restrict__ qkv, const float* __restrict__ state,
                float* __restrict__ out) {
    extern __shared__ float smf[];
    float* sq = smf;
    float* sk = sq + 4160;
    float* sv = sk + 4160;
    float* Sc = sv + 4160;
    float* Ss = Sc + 4160;
    float* AS = Ss + 4160;
    float* cw = AS + 4160;
    float* sw = cw + 64;
    float* Zc = sw + 64;
    float* Zs = Zc + 64;
    float* normp = Zs + 64;
    float* normF = normp + 256;

    int blk = blockIdx.x;
    int c = blk % NCH;
    int bh = blk / NCH;
    int b = bh / HH, h = bh % HH;
    int tid = threadIdx.x;

    const float* st = state + ((size_t)bh * NCH + c) * ST_STRIDE;

    for (int idx = tid; idx < CHK * 16; idx += 256) {
        int j = idx >> 4;
        int dd = (idx & 15) << 2;
        int l = c * CHK + j;
        const float* base = qkv + (size_t)(b * LL + l) * (3 * EE) + h * DD;
        float4 qv = *(const float4*)(base + dd);
        float4 kv = *(const float4*)(base + EE + dd);
        float4 vv = *(const float4*)(base + 2 * EE + dd);
        int ro = j * 65 + dd;
        sq[ro + 0] = fmaxf(qv.x, 0.f); sq[ro + 1] = fmaxf(qv.y, 0.f);
        sq[ro + 2] = fmaxf(qv.z, 0.f); sq[ro + 3] = fmaxf(qv.w, 0.f);
        sk[ro + 0] = fmaxf(kv.x, 0.f); sk[ro + 1] = fmaxf(kv.y, 0.f);
        sk[ro + 2] = fmaxf(kv.z, 0.f); sk[ro + 3] = fmaxf(kv.w, 0.f);
        sv[ro + 0] = vv.x; sv[ro + 1] = vv.y; sv[ro + 2] = vv.z; sv[ro + 3] = vv.w;
        int flat = idx << 2;
        int d = flat >> 6, e = flat & 63;
        float4 scv = *(const float4*)(st + flat);
        float4 ssv = *(const float4*)(st + 4096 + flat);
        int so = d * 65 + e;
        Sc[so + 0] = scv.x; Sc[so + 1] = scv.y; Sc[so + 2] = scv.z; Sc[so + 3] = scv.w;
        Ss[so + 0] = ssv.x; Ss[so + 1] = ssv.y; Ss[so + 2] = ssv.z; Ss[so + 3] = ssv.w;
    }
    if (tid < CHK) {
        float ang = 1.5707963267948966f * (float)(c * CHK + tid) / (float)LL;
        cw[tid] = cosf(ang);
        sw[tid] = sinf(ang);
        Zc[tid] = st[8192 + tid];
        Zs[tid] = st[8256 + tid];
    }
    __syncthreads();

    {
        int jc = tid >> 6;
        int i  = tid & 63;
        float acc[16];
        #pragma unroll
        for (int r = 0; r < 16; r++) acc[r] = 0.f;
        for (int d = 0; d < DD; d++) {
            float qv = sq[i * 65 + d];
            #pragma unroll
            for (int r = 0; r < 16; r++)
                acc[r] = fmaf(qv, sk[(jc * 16 + r) * 65 + d], acc[r]);
        }
        float cwi = cw[i], swi = sw[i];
        float rsum = 0.f;
        #pragma unroll
        for (int r = 0; r < 16; r++) {
            int j = jc * 16 + r;
            float wgt = (j <= i) ? (cwi * cw[j] + swi * sw[j]) : 0.f;
            float a = acc[r] * wgt;
            AS[i * 65 + j] = a;
            rsum += a;
        }
        normp[jc * 64 + i] = rsum;
    }
    __syncthreads();

    if (tid < 64) {
        int i = tid;
        float n = normp[i] + normp[64 + i] + normp[128 + i] + normp[192 + i];
        float dc = 0.f, ds = 0.f;
        for (int d = 0; d < DD; d++) {
            float qv = sq[i * 65 + d];
            dc = fmaf(qv, Zc[d], dc);
            ds = fmaf(qv, Zs[d], ds);
        }
        normF[i] = n + cw[i] * dc + sw[i] * ds;
    }

    int ec = tid >> 6;
    int i2 = tid & 63;
    int e0 = ec * 16;
    float accO[16], accC2[16], accS2[16];
    #pragma unroll
    for (int r = 0; r < 16; r++) { accO[r] = 0.f; accC2[r] = 0.f; accS2[r] = 0.f; }

    for (int j = 0; j < CHK; j++) {
        float av = AS[i2 * 65 + j];
        #pragma unroll
        for (int r = 0; r < 16; r++)
            accO[r] = fmaf(av, sv[j * 65 + e0 + r], accO[r]);
    }
    for (int d = 0; d < DD; d++) {
        float qv = sq[i2 * 65 + d];
        #pragma unroll
        for (int r = 0; r < 16; r++) {
            accC2[r] = fmaf(qv, Sc[d * 65 + e0 + r], accC2[r]);
            accS2[r] = fmaf(qv, Ss[d * 65 + e0 + r], accS2[r]);
        }
    }
    __syncthreads();

    float nrm = normF[i2] + 1e-6f;
    float inv = 1.0f / nrm;
    float cwi = cw[i2], swi = sw[i2];
    int lg = c * CHK + i2;
    float* op = out + (size_t)(b * LL + lg) * EE + h * DD + e0;
    #pragma unroll
    for (int r4 = 0; r4 < 4; r4++) {
        float4 o;
        o.x = tf32f((accO[r4*4+0] + cwi*accC2[r4*4+0] + swi*accS2[r4*4+0]) * inv);
        o.y = tf32f((accO[r4*4+1] + cwi*accC2[r4*4+1] + swi*accS2[r4*4+1]) * inv);
        o.z = tf32f((accO[r4*4+2] + cwi*accC2[r4*4+2] + swi*accS2[r4*4+2]) * inv);
        o.w = tf32f((accO[r4*4+3] + cwi*accC2[r4*4+3] + swi*accS2[r4*4+3]) * inv);
        *(float4*)(op + r4 * 4) = o;
    }
}

// ---------------------------------------------------------------------------
// launch
// ---------------------------------------------------------------------------
extern "C" void kernel_launch(void* const* d_in, const int* in_sizes, int n_in,
                              void* d_out, int out_size) {
    const float* x       = (const float*)d_in[0];
    const float* qkv_w   = (const float*)d_in[1];
    const float* qkv_b   = (const float*)d_in[2];
    const float* out_w   = (const float*)d_in[3];
    const float* out_b   = (const float*)d_in[4];
    const float* norm1_w = (const float*)d_in[5];
    const float* norm2_w = (const float*)d_in[6];
    const float* mlp_w1  = (const float*)d_in[7];
    const float* mlp_b1  = (const float*)d_in[8];
    const float* mlp_w2  = (const float*)d_in[9];
    const float* mlp_b2  = (const float*)d_in[10];
    float* out = (float*)d_out;

    float *xn, *qkv, *attn, *hbuf, *mid, *state;
    cudaGetSymbolAddress((void**)&xn, g_xn);
    cudaGetSymbolAddress((void**)&qkv, g_qkv);
    cudaGetSymbolAddress((void**)&attn, g_attn);
    cudaGetSymbolAddress((void**)&hbuf, g_h);
    cudaGetSymbolAddress((void**)&mid, g_mid);
    cudaGetSymbolAddress((void**)&state, g_state);

    cudaFuncSetAttribute(attn_out_kernel,
                         cudaFuncAttributeMaxDynamicSharedMemorySize,
                         ATTN_SMEM_BYTES);
    cudaFuncSetAttribute(tgemm_kernel,
                         cudaFuncAttributeMaxDynamicSharedMemorySize,
                         GEMM_SMEM_BYTES);

    // 1. xn = tf32(rmsnorm(x, norm1_w))
    rmsnorm_kernel<<<ROWS, 256>>>(x, norm1_w, xn, 1);
    // 2. qkv = xn @ qkv_w + qkv_b (fp32, consumed by attention)
    tgemm_kernel<<<dim3(3 * EE / 128, ROWS / 128), 512, GEMM_SMEM_BYTES>>>(
        xn, qkv_w, qkv_b, nullptr, qkv, ROWS, 3 * EE, EE, 0, 0);
    // 3-5. cosformer attention (chunked); attn emitted as tf32 bits
    attn_chunk_state<<<BB * HH * NCH, 256>>>(qkv, state);
    attn_prefix<<<dim3((ST_STRIDE + 255) / 256, BB * HH), 256>>>(state);
    attn_out_kernel<<<BB * HH * NCH, 256, ATTN_SMEM_BYTES>>>(qkv, state, attn);
    // 6. h = attn @ out_w + out_b + x (fp32: rmsnorm + residual consumer)
    tgemm_kernel<<<dim3(EE / 128, ROWS / 128), 512, GEMM_SMEM_BYTES>>>(
        attn, out_w, out_b, x, hbuf, ROWS, EE, EE, 2, 0);
    // 7. xn = tf32(rmsnorm(h, norm2_w))
    rmsnorm_kernel<<<ROWS, 256>>>(hbuf, norm2_w, xn, 1);
    // 8. mid = tf32(gelu(xn @ mlp_w1 + mlp_b1))
    tgemm_kernel<<<dim3(4 * EE / 128, ROWS / 128), 512, GEMM_SMEM_BYTES>>>(
        xn, mlp_w1, mlp_b1, nullptr, mid, ROWS, 4 * EE, EE, 1, 1);
    // 9. out = mid @ mlp_w2 + mlp_b2 + h (fp32 final)
    tgemm_kernel<<<dim3(EE / 128, ROWS / 128), 512, GEMM_SMEM_BYTES>>>(
        mid, mlp_w2, mlp_b2, hbuf, out, ROWS, EE, 4 * EE, 2, 0);
}

// round 10
// speedup vs baseline: 1.7377x; 1.3268x over previous
#include <cuda_runtime.h>
#include <cuda_fp16.h>
#include <math.h>
#include <stdint.h>

// Problem constants
#define BB 2
#define LL 1024
#define EE 1024
#define HH 16
#define DD 64
#define NCH 16
#define CHK 64
#define ST_STRIDE 8320
#define ROWS (BB*LL)    // 2048

// GEMM smem (half2 words), double buffered:
//   A [128 rows][AP=20 words]  (16 data words = 32 halves of k, +4 pad)
//   B [16 k2-rows][BP=136 words]
#define AP 20
#define BP 136
#define AWORDS (128 * AP)          // 2560
#define BWORDS (16 * BP)           // 2176
#define STW (AWORDS + BWORDS)      // 4736 words
#define GEMM_SMEM_BYTES (2 * STW * 4)  // 37888

// Scratch (device globals; no allocs allowed)
__device__ float  g_qkv[ROWS * 3 * EE];
__device__ float  g_h[ROWS * EE];
__device__ float  g_state[BB * HH * NCH * ST_STRIDE];
__device__ __half g_xnh[ROWS * EE];
__device__ __half g_attnh[ROWS * EE];
__device__ __half g_midh[ROWS * 4 * EE];

// ---------------------------------------------------------------------------
// helpers
// ---------------------------------------------------------------------------
__device__ __forceinline__ uint32_t pack_h2(float lo, float hi) {
    __half2 h = __floats2half2_rn(lo, hi);
    return *reinterpret_cast<uint32_t*>(&h);
}

__device__ __forceinline__ void mma_f16(float* c, const uint32_t* a,
                                        uint32_t b0, uint32_t b1) {
    asm volatile(
        "mma.sync.aligned.m16n8k16.row.col.f32.f16.f16.f32 "
        "{%0,%1,%2,%3}, {%4,%5,%6,%7}, {%8,%9}, {%0,%1,%2,%3};"
        : "+f"(c[0]), "+f"(c[1]), "+f"(c[2]), "+f"(c[3])
        : "r"(a[0]), "r"(a[1]), "r"(a[2]), "r"(a[3]),
          "r"(b0), "r"(b1));
}

__device__ __forceinline__ void ldsm_x4(uint32_t* d, uint32_t saddr) {
    asm volatile("ldmatrix.sync.aligned.m8n8.x4.shared.b16 {%0,%1,%2,%3}, [%4];"
                 : "=r"(d[0]), "=r"(d[1]), "=r"(d[2]), "=r"(d[3])
                 : "r"(saddr));
}

// ---------------------------------------------------------------------------
// FP16 mma.sync GEMM (R4 skeleton): LDG->reg->STS double buffer, 1 sync/tile.
//  - A: __half [M][K], pre-converted by producers. Copied as raw 16B chunks.
//  - W: fp32 [K][N], converted to half2 at STS ([k/2][n] packing).
//  - A frags via native b16 ldmatrix.x4; B frags via conflict-free scalar LDS.
// C[M,N] = A @ W + bias (+gelu | +res). 128x128 tile, BK=32, 8 warps (2x4),
// warp tile 64x32, k16 steps = 2 per tile.
// epi: 0=bias 1=bias+gelu 2=bias+res. ohalf: write __half output to Ch.
// ---------------------------------------------------------------------------
__global__ void __launch_bounds__(256)
tgemm_kernel(const __half* __restrict__ A, const float* __restrict__ W,
             const float* __restrict__ bias, const float* __restrict__ res,
             float* __restrict__ C, __half* __restrict__ Ch,
             int M, int N, int K, int epi, int ohalf) {
    extern __shared__ uint32_t smu[];
    uint32_t sbase = (uint32_t)__cvta_generic_to_shared(smu);

    int tid = threadIdx.x;
    int bx = blockIdx.x;   // N tile
    int by = blockIdx.y;   // M tile
    int warp = tid >> 5;
    int lane = tid & 31;
    int wm = warp >> 2;    // 0..1 (64 rows)
    int wn = warp & 3;     // 0..3 (32 cols)
    int g  = lane >> 2;    // 0..7
    int tg = lane & 3;     // 0..3

    float acc[4][4][4];
    #pragma unroll
    for (int mi = 0; mi < 4; mi++)
        #pragma unroll
        for (int ni = 0; ni < 4; ni++)
            #pragma unroll
            for (int r = 0; r < 4; r++) acc[mi][ni][r] = 0.f;

    // A copy: row am = tid>>1 (0..127), half-col = (tid&1)*16; 2 x uint4 (32B)
    int am = tid >> 1;
    int ah = (tid & 1) * 16;                 // half offset
    const __half* Ag = A + (size_t)(by * 128 + am) * K + ah;
    // W copy: k-pair kk = tid>>4 (0..15), n0 = (tid&15)*8; rows 2kk, 2kk+1
    int kk = tid >> 4;
    int n0c = (tid & 15) * 8;
    const float* Wg = W + (size_t)(2 * kk) * N + bx * 128 + n0c;

    // ldmatrix lane offset (words): row = (sel&1)*8 + rr, k-half word = (sel>>1)*4
    int sel = lane >> 3;
    int rr  = lane & 7;
    int aLaneOff = ((sel & 1) * 8 + rr) * AP + (sel >> 1) * 4;

    int m0base = wm * 64;
    int n0base = wn * 32;
    int nT = K >> 5;

    uint4 aR0, aR1;
    float4 w0a, w0b, w1a, w1b;
    auto ldg = [&](int t) {
        const __half* Asrc = Ag + t * 32;
        aR0 = *(const uint4*)(Asrc);
        aR1 = *(const uint4*)(Asrc + 8);
        const float* r0 = Wg + (size_t)(t * 32) * N;
        const float* r1 = r0 + N;
        w0a = *(const float4*)(r0);  w0b = *(const float4*)(r0 + 4);
        w1a = *(const float4*)(r1);  w1b = *(const float4*)(r1 + 4);
    };
    auto sts = [&](int buf) {
        uint32_t* sA = smu + buf * STW;
        uint32_t* sB = sA + AWORDS;
        int aw = am * AP + (tid & 1) * 8;
        *(uint4*)&sA[aw]     = aR0;
        *(uint4*)&sA[aw + 4] = aR1;
        uint4 u0, u1;
        u0.x = pack_h2(w0a.x, w1a.x); u0.y = pack_h2(w0a.y, w1a.y);
        u0.z = pack_h2(w0a.z, w1a.z); u0.w = pack_h2(w0a.w, w1a.w);
        u1.x = pack_h2(w0b.x, w1b.x); u1.y = pack_h2(w0b.y, w1b.y);
        u1.z = pack_h2(w0b.z, w1b.z); u1.w = pack_h2(w0b.w, w1b.w);
        int bw = kk * BP + n0c;
        *(uint4*)&sB[bw]     = u0;
        *(uint4*)&sB[bw + 4] = u1;
    };

    // prologue
    ldg(0);
    sts(0);
    ldg(1);
    __syncthreads();

    for (int t = 0; t < nT; t++) {
        if (t + 1 < nT) sts((t + 1) & 1);
        if (t + 2 < nT) ldg(t + 2);

        uint32_t sA = sbase + (uint32_t)((t & 1) * STW) * 4u;
        const uint32_t* sB = smu + (t & 1) * STW + AWORDS;

        #pragma unroll
        for (int ks = 0; ks < 2; ks++) {        // two k16 steps
            int kw = ks * 8;                    // word (half2) offset
            uint32_t af[4][4];
            #pragma unroll
            for (int mi = 0; mi < 4; mi++)
                ldsm_x4(af[mi], sA + 4u * (uint32_t)((m0base + mi * 16) * AP + kw + aLaneOff));
            uint32_t bf[4][2];
            #pragma unroll
            for (int ni = 0; ni < 4; ni++) {
                int idx = (kw + tg) * BP + n0base + ni * 8 + g;
                bf[ni][0] = sB[idx];
                bf[ni][1] = sB[idx + 4 * BP];
            }
            #pragma unroll
            for (int mi = 0; mi < 4; mi++)
                #pragma unroll
                for (int ni = 0; ni < 4; ni++)
                    mma_f16(acc[mi][ni], af[mi], bf[ni][0], bf[ni][1]);
        }
        __syncthreads();
    }

    // Epilogue. c0:(g, 2tg) c1:(g, 2tg+1) c2:(g+8, 2tg) c3:(g+8, 2tg+1)
    #pragma unroll
    for (int mi = 0; mi < 4; mi++) {
        #pragma unroll
        for (int ni = 0; ni < 4; ni++) {
            int col = bx * 128 + wn * 32 + ni * 8 + tg * 2;
            float b0 = bias[col], b1 = bias[col + 1];
            #pragma unroll
            for (int half = 0; half < 2; half++) {
                int orow = by * 128 + wm * 64 + mi * 16 + g + half * 8;
                size_t off = (size_t)orow * N + col;
                float v0 = acc[mi][ni][half * 2 + 0] + b0;
                float v1 = acc[mi][ni][half * 2 + 1] + b1;
                if (epi == 1) {
                    float u0 = v0 * (0.7978845608028654f + 0.035677408136300125f * v0 * v0);
                    float u1 = v1 * (0.7978845608028654f + 0.035677408136300125f * v1 * v1);
                    v0 = 0.5f * v0 * (1.f + tanhf(u0));
                    v1 = 0.5f * v1 * (1.f + tanhf(u1));
                } else if (epi == 2) {
                    v0 += res[off];
                    v1 += res[off + 1];
                }
                if (ohalf) {
                    *(uint32_t*)(Ch + off) = pack_h2(v0, v1);
                } else {
                    *(float2*)(C + off) = make_float2(v0, v1);
                }
            }
        }
    }
}

// ---------------------------------------------------------------------------
// RMSNorm -> __half output (GEMM A input)
// ---------------------------------------------------------------------------
__global__ void rmsnorm_kernel(const float* __restrict__ x,
                               const float* __restrict__ w,
                               __half* __restrict__ out) {
    int row = blockIdx.x;
    int tid = threadIdx.x;
    const float4* xr = (const float4*)(x + (size_t)row * EE);
    float4 v = xr[tid];
    float ss = v.x*v.x + v.y*v.y + v.z*v.z + v.w*v.w;
    #pragma unroll
    for (int o = 16; o; o >>= 1) ss += __shfl_xor_sync(0xffffffffu, ss, o);
    __shared__ float red[8];
    if ((tid & 31) == 0) red[tid >> 5] = ss;
    __syncthreads();
    float tot = 0.f;
    #pragma unroll
    for (int i = 0; i < 8; i++) tot += red[i];
    float scale = rsqrtf(tot * (1.0f / (float)EE) + 1e-6f);
    float4 wv = ((const float4*)w)[tid];
    uint2 o;
    o.x = pack_h2(v.x * scale * wv.x, v.y * scale * wv.y);
    o.y = pack_h2(v.z * scale * wv.z, v.w * scale * wv.w);
    *(uint2*)(out + (size_t)row * EE + tid * 4) = o;
}

// ---------------------------------------------------------------------------
// Attention pass A: per-chunk state sums.
// ---------------------------------------------------------------------------
__global__ void __launch_bounds__(256)
attn_chunk_state(const float* __restrict__ qkv, float* __restrict__ state) {
    int blk = blockIdx.x;
    int c = blk % NCH;
    int bh = blk / NCH;
    int b = bh / HH, h = bh % HH;

    __shared__ float sk[CHK][DD + 1];
    __shared__ float sv[CHK][DD + 1];
    __shared__ float cw[CHK], sw[CHK];

    int tid = threadIdx.x;
    for (int idx = tid; idx < CHK * 16; idx += 256) {
        int j = idx >> 4;
        int dd = (idx & 15) << 2;
        int l = c * CHK + j;
        const float* base = qkv + (size_t)(b * LL + l) * (3 * EE) + h * DD;
        float4 kv = *(const float4*)(base + EE + dd);
        float4 vv = *(const float4*)(base + 2 * EE + dd);
        sk[j][dd + 0] = fmaxf(kv.x, 0.f);
        sk[j][dd + 1] = fmaxf(kv.y, 0.f);
        sk[j][dd + 2] = fmaxf(kv.z, 0.f);
        sk[j][dd + 3] = fmaxf(kv.w, 0.f);
        sv[j][dd + 0] = vv.x;
        sv[j][dd + 1] = vv.y;
        sv[j][dd + 2] = vv.z;
        sv[j][dd + 3] = vv.w;
    }
    if (tid < CHK) {
        float ang = 1.5707963267948966f * (float)(c * CHK + tid) / (float)LL;
        cw[tid] = cosf(ang);
        sw[tid] = sinf(ang);
    }
    __syncthreads();

    int e  = tid & 63;
    int d0 = (tid >> 6) * 16;
    float accC[16], accS[16];
    #pragma unroll
    for (int r = 0; r < 16; r++) { accC[r] = 0.f; accS[r] = 0.f; }

    for (int j = 0; j < CHK; j++) {
        float ve = sv[j][e];
        float t1 = ve * cw[j];
        float t2 = ve * sw[j];
        #pragma unroll
        for (int r = 0; r < 16; r++) {
            float kd = sk[j][d0 + r];
            accC[r] = fmaf(kd, t1, accC[r]);
            accS[r] = fmaf(kd, t2, accS[r]);
        }
    }

    float* st = state + ((size_t)bh * NCH + c) * ST_STRIDE;
    #pragma unroll
    for (int r = 0; r < 16; r++) {
        st[(d0 + r) * 64 + e]        = accC[r];
        st[4096 + (d0 + r) * 64 + e] = accS[r];
    }
    if (tid < DD) {
        float zc = 0.f, zs = 0.f;
        for (int j = 0; j < CHK; j++) {
            float kd = sk[j][tid];
            zc = fmaf(kd, cw[j], zc);
            zs = fmaf(kd, sw[j], zs);
        }
        st[8192 + tid] = zc;
        st[8256 + tid] = zs;
    }
}

// ---------------------------------------------------------------------------
// Attention pass B: exclusive prefix over chunks (in-place).
// ---------------------------------------------------------------------------
__global__ void attn_prefix(float* __restrict__ state) {
    int bh  = blockIdx.y;
    int idx = blockIdx.x * 256 + threadIdx.x;
    if (idx >= ST_STRIDE) return;
    float* p = state + (size_t)bh * NCH * ST_STRIDE + idx;
    float vals[NCH];
    #pragma unroll
    for (int cc = 0; cc < NCH; cc++) vals[cc] = p[(size_t)cc * ST_STRIDE];
    float run = 0.f;
    #pragma unroll
    for (int cc = 0; cc < NCH; cc++) {
        p[(size_t)cc * ST_STRIDE] = run;
        run += vals[cc];
    }
}

// ---------------------------------------------------------------------------
// Attention pass C: per-chunk output -> __half (out-proj GEMM A input).
// ---------------------------------------------------------------------------
#define ATTN_SMEM_FLOATS (6 * 64 * 65 + 64 + 64 + 64 + 64 + 256 + 64)
#define ATTN_SMEM_BYTES (ATTN_SMEM_FLOATS * 4)

__global__ void __launch_bounds__(256)
attn_out_kernel(const float* __restrict__ qkv, const float* __restrict__ state,
                __half* __restrict__ out) {
    extern __shared__ float smf[];
    float* sq = smf;
    float* sk = sq + 4160;
    float* sv = sk + 4160;
    float* Sc = sv + 4160;
    float* Ss = Sc + 4160;
    float* AS = Ss + 4160;
    float* cw = AS + 4160;
    float* sw = cw + 64;
    float* Zc = sw + 64;
    float* Zs = Zc + 64;
    float* normp = Zs + 64;
    float* normF = normp + 256;

    int blk = blockIdx.x;
    int c = blk % NCH;
    int bh = blk / NCH;
    int b = bh / HH, h = bh % HH;
    int tid = threadIdx.x;

    const float* st = state + ((size_t)bh * NCH + c) * ST_STRIDE;

    for (int idx = tid; idx < CHK * 16; idx += 256) {
        int j = idx >> 4;
        int dd = (idx & 15) << 2;
        int l = c * CHK + j;
        const float* base = qkv + (size_t)(b * LL + l) * (3 * EE) + h * DD;
        float4 qv = *(const float4*)(base + dd);
        float4 kv = *(const float4*)(base + EE + dd);
        float4 vv = *(const float4*)(base + 2 * EE + dd);
        int ro = j * 65 + dd;
        sq[ro + 0] = fmaxf(qv.x, 0.f); sq[ro + 1] = fmaxf(qv.y, 0.f);
        sq[ro + 2] = fmaxf(qv.z, 0.f); sq[ro + 3] = fmaxf(qv.w, 0.f);
        sk[ro + 0] = fmaxf(kv.x, 0.f); sk[ro + 1] = fmaxf(kv.y, 0.f);
        sk[ro + 2] = fmaxf(kv.z, 0.f); sk[ro + 3] = fmaxf(kv.w, 0.f);
        sv[ro + 0] = vv.x; sv[ro + 1] = vv.y; sv[ro + 2] = vv.z; sv[ro + 3] = vv.w;
        int flat = idx << 2;
        int d = flat >> 6, e = flat & 63;
        float4 scv = *(const float4*)(st + flat);
        float4 ssv = *(const float4*)(st + 4096 + flat);
        int so = d * 65 + e;
        Sc[so + 0] = scv.x; Sc[so + 1] = scv.y; Sc[so + 2] = scv.z; Sc[so + 3] = scv.w;
        Ss[so + 0] = ssv.x; Ss[so + 1] = ssv.y; Ss[so + 2] = ssv.z; Ss[so + 3] = ssv.w;
    }
    if (tid < CHK) {
        float ang = 1.5707963267948966f * (float)(c * CHK + tid) / (float)LL;
        cw[tid] = cosf(ang);
        sw[tid] = sinf(ang);
        Zc[tid] = st[8192 + tid];
        Zs[tid] = st[8256 + tid];
    }
    __syncthreads();

    {
        int jc = tid >> 6;
        int i  = tid & 63;
        float acc[16];
        #pragma unroll
        for (int r = 0; r < 16; r++) acc[r] = 0.f;
        for (int d = 0; d < DD; d++) {
            float qv = sq[i * 65 + d];
            #pragma unroll
            for (int r = 0; r < 16; r++)
                acc[r] = fmaf(qv, sk[(jc * 16 + r) * 65 + d], acc[r]);
        }
        float cwi = cw[i], swi = sw[i];
        float rsum = 0.f;
        #pragma unroll
        for (int r = 0; r < 16; r++) {
            int j = jc * 16 + r;
            float wgt = (j <= i) ? (cwi * cw[j] + swi * sw[j]) : 0.f;
            float a = acc[r] * wgt;
            AS[i * 65 + j] = a;
            rsum += a;
        }
        normp[jc * 64 + i] = rsum;
    }
    __syncthreads();

    if (tid < 64) {
        int i = tid;
        float n = normp[i] + normp[64 + i] + normp[128 + i] + normp[192 + i];
        float dc = 0.f, ds = 0.f;
        for (int d = 0; d < DD; d++) {
            float qv = sq[i * 65 + d];
            dc = fmaf(qv, Zc[d], dc);
            ds = fmaf(qv, Zs[d], ds);
        }
        normF[i] = n + cw[i] * dc + sw[i] * ds;
    }

    int ec = tid >> 6;
    int i2 = tid & 63;
    int e0 = ec * 16;
    float accO[16], accC2[16], accS2[16];
    #pragma unroll
    for (int r = 0; r < 16; r++) { accO[r] = 0.f; accC2[r] = 0.f; accS2[r] = 0.f; }

    for (int j = 0; j < CHK; j++) {
        float av = AS[i2 * 65 + j];
        #pragma unroll
        for (int r = 0; r < 16; r++)
            accO[r] = fmaf(av, sv[j * 65 + e0 + r], accO[r]);
    }
    for (int d = 0; d < DD; d++) {
        float qv = sq[i2 * 65 + d];
        #pragma unroll
        for (int r = 0; r < 16; r++) {
            accC2[r] = fmaf(qv, Sc[d * 65 + e0 + r], accC2[r]);
            accS2[r] = fmaf(qv, Ss[d * 65 + e0 + r], accS2[r]);
        }
    }
    __syncthreads();

    float nrm = normF[i2] + 1e-6f;
    float inv = 1.0f / nrm;
    float cwi = cw[i2], swi = sw[i2];
    int lg = c * CHK + i2;
    __half* op = out + (size_t)(b * LL + lg) * EE + h * DD + e0;
    #pragma unroll
    for (int r4 = 0; r4 < 4; r4++) {
        float v0 = (accO[r4*4+0] + cwi*accC2[r4*4+0] + swi*accS2[r4*4+0]) * inv;
        float v1 = (accO[r4*4+1] + cwi*accC2[r4*4+1] + swi*accS2[r4*4+1]) * inv;
        float v2 = (accO[r4*4+2] + cwi*accC2[r4*4+2] + swi*accS2[r4*4+2]) * inv;
        float v3 = (accO[r4*4+3] + cwi*accC2[r4*4+3] + swi*accS2[r4*4+3]) * inv;
        uint2 o;
        o.x = pack_h2(v0, v1);
        o.y = pack_h2(v2, v3);
        *(uint2*)(op + r4 * 4) = o;
    }
}

// ---------------------------------------------------------------------------
// launch
// ---------------------------------------------------------------------------
extern "C" void kernel_launch(void* const* d_in, const int* in_sizes, int n_in,
                              void* d_out, int out_size) {
    const float* x       = (const float*)d_in[0];
    const float* qkv_w   = (const float*)d_in[1];
    const float* qkv_b   = (const float*)d_in[2];
    const float* out_w   = (const float*)d_in[3];
    const float* out_b   = (const float*)d_in[4];
    const float* norm1_w = (const float*)d_in[5];
    const float* norm2_w = (const float*)d_in[6];
    const float* mlp_w1  = (const float*)d_in[7];
    const float* mlp_b1  = (const float*)d_in[8];
    const float* mlp_w2  = (const float*)d_in[9];
    const float* mlp_b2  = (const float*)d_in[10];
    float* out = (float*)d_out;

    float *qkv, *hbuf, *state;
    __half *xnh, *attnh, *midh;
    cudaGetSymbolAddress((void**)&qkv, g_qkv);
    cudaGetSymbolAddress((void**)&hbuf, g_h);
    cudaGetSymbolAddress((void**)&state, g_state);
    cudaGetSymbolAddress((void**)&xnh, g_xnh);
    cudaGetSymbolAddress((void**)&attnh, g_attnh);
    cudaGetSymbolAddress((void**)&midh, g_midh);

    cudaFuncSetAttribute(attn_out_kernel,
                         cudaFuncAttributeMaxDynamicSharedMemorySize,
                         ATTN_SMEM_BYTES);
    cudaFuncSetAttribute(tgemm_kernel,
                         cudaFuncAttributeMaxDynamicSharedMemorySize,
                         GEMM_SMEM_BYTES);

    // 1. xnh = half(rmsnorm(x, norm1_w))
    rmsnorm_kernel<<<ROWS, 256>>>(x, norm1_w, xnh);
    // 2. qkv = xnh @ qkv_w + qkv_b (fp32 out for attention)
    tgemm_kernel<<<dim3(3 * EE / 128, ROWS / 128), 256, GEMM_SMEM_BYTES>>>(
        xnh, qkv_w, qkv_b, nullptr, qkv, nullptr, ROWS, 3 * EE, EE, 0, 0);
    // 3-5. cosformer attention (chunked); attnh emitted as half
    attn_chunk_state<<<BB * HH * NCH, 256>>>(qkv, state);
    attn_prefix<<<dim3((ST_STRIDE + 255) / 256, BB * HH), 256>>>(state);
    attn_out_kernel<<<BB * HH * NCH, 256, ATTN_SMEM_BYTES>>>(qkv, state, attnh);
    // 6. h = attnh @ out_w + out_b + x (fp32)
    tgemm_kernel<<<dim3(EE / 128, ROWS / 128), 256, GEMM_SMEM_BYTES>>>(
        attnh, out_w, out_b, x, hbuf, nullptr, ROWS, EE, EE, 2, 0);
    // 7. xnh = half(rmsnorm(h, norm2_w))
    rmsnorm_kernel<<<ROWS, 256>>>(hbuf, norm2_w, xnh);
    // 8. midh = half(gelu(xnh @ mlp_w1 + mlp_b1))
    tgemm_kernel<<<dim3(4 * EE / 128, ROWS / 128), 256, GEMM_SMEM_BYTES>>>(
        xnh, mlp_w1, mlp_b1, nullptr, nullptr, midh, ROWS, 4 * EE, EE, 1, 1);
    // 9. out = midh @ mlp_w2 + mlp_b2 + h (fp32 final)
    tgemm_kernel<<<dim3(EE / 128, ROWS / 128), 256, GEMM_SMEM_BYTES>>>(
        midh, mlp_w2, mlp_b2, hbuf, out, nullptr, ROWS, EE, 4 * EE, 2, 0);
}

// round 11
// speedup vs baseline: 2.0106x; 1.1571x over previous
#include <cuda_runtime.h>
#include <cuda_fp16.h>
#include <math.h>
#include <stdint.h>

// Problem constants
#define BB 2
#define LL 1024
#define EE 1024
#define HH 16
#define DD 64
#define NCH 16
#define CHK 64
#define ST_STRIDE 8320
#define ROWS (BB*LL)    // 2048

// GEMM smem (half2 words), double buffered:
//   A [128 rows][AP=20 words], B [16 k2-rows][BP=136 words]
#define AP 20
#define BP 136
#define AWORDS (128 * AP)          // 2560
#define BWORDS (16 * BP)           // 2176
#define STW (AWORDS + BWORDS)      // 4736 words
#define GEMM_SMEM_BYTES (2 * STW * 4)  // 37888

// Scratch (device globals; no allocs allowed)
__device__ float  g_qkv[ROWS * 3 * EE];
__device__ float  g_h[ROWS * EE];
__device__ float  g_state[BB * HH * NCH * ST_STRIDE];
__device__ __half g_xnh[ROWS * EE];
__device__ __half g_attnh[ROWS * EE];
__device__ __half g_midh[ROWS * 4 * EE];
// packed half2 weights: [k/2][n] words; qkv | out | mlp1 | mlp2
#define WOFF_QKV 0
#define WOFF_OUT (WOFF_QKV + (EE/2) * 3 * EE)      // 1,572,864 words
#define WOFF_W1  (WOFF_OUT + (EE/2) * EE)          // +524,288
#define WOFF_W2  (WOFF_W1  + (EE/2) * 4 * EE)      // +2,097,152
#define WTOTAL   (WOFF_W2  + (2 * EE) * EE)        // +2,097,152 = 6,291,456 words
__device__ uint32_t g_wh[WTOTAL];                  // 24 MB

// ---------------------------------------------------------------------------
// helpers
// ---------------------------------------------------------------------------
__device__ __forceinline__ uint32_t pack_h2(float lo, float hi) {
    __half2 h = __floats2half2_rn(lo, hi);
    return *reinterpret_cast<uint32_t*>(&h);
}

__device__ __forceinline__ void mma_f16(float* c, const uint32_t* a,
                                        uint32_t b0, uint32_t b1) {
    asm volatile(
        "mma.sync.aligned.m16n8k16.row.col.f32.f16.f16.f32 "
        "{%0,%1,%2,%3}, {%4,%5,%6,%7}, {%8,%9}, {%0,%1,%2,%3};"
        : "+f"(c[0]), "+f"(c[1]), "+f"(c[2]), "+f"(c[3])
        : "r"(a[0]), "r"(a[1]), "r"(a[2]), "r"(a[3]),
          "r"(b0), "r"(b1));
}

__device__ __forceinline__ void ldsm_x4(uint32_t* d, uint32_t saddr) {
    asm volatile("ldmatrix.sync.aligned.m8n8.x4.shared.b16 {%0,%1,%2,%3}, [%4];"
                 : "=r"(d[0]), "=r"(d[1]), "=r"(d[2]), "=r"(d[3])
                 : "r"(saddr));
}

// ---------------------------------------------------------------------------
// Weight convert: fp32 [K][N] -> packed half2 words [(k/2)][n]
// word (r, n) = half2(W[2r][n], W[2r+1][n]). Streaming, coalesced.
// ---------------------------------------------------------------------------
__global__ void wconv_kernel(const float* __restrict__ in,
                             uint32_t* __restrict__ out, int K, int N) {
    int idx = blockIdx.x * 256 + threadIdx.x;       // over (K/2)*(N/4)
    int nq = N >> 2;
    int r = idx / nq;
    int n = (idx - r * nq) << 2;
    if (r >= (K >> 1)) return;
    const float* r0 = in + (size_t)(2 * r) * N + n;
    const float* r1 = r0 + N;
    float4 a = *(const float4*)r0;
    float4 b = *(const float4*)r1;
    uint4 u;
    u.x = pack_h2(a.x, b.x);
    u.y = pack_h2(a.y, b.y);
    u.z = pack_h2(a.z, b.z);
    u.w = pack_h2(a.w, b.w);
    *(uint4*)(out + (size_t)r * N + n) = u;
}

// ---------------------------------------------------------------------------
// FP16 mma.sync GEMM: LDG->reg->STS double buffer, 1 sync/tile, 2 CTAs/SM.
//  - A: __half [M][K] (producers emit half). Raw 16B copies.
//  - Wh: packed half2 words [(K/2)][N] (pre-converted). Raw 16B copies.
//  - A frags via native b16 ldmatrix.x4; B frags via conflict-free scalar LDS.
// C[M,N] = A @ W + bias (+gelu | +res). 128x128 tile, BK=32, 8 warps (2x4),
// warp tile 64x32, two k16 steps per tile.
// epi: 0=bias 1=bias+gelu 2=bias+res. ohalf: write __half output to Ch.
// ---------------------------------------------------------------------------
__global__ void __launch_bounds__(256, 2)
tgemm_kernel(const __half* __restrict__ A, const uint32_t* __restrict__ Wh,
             const float* __restrict__ bias, const float* __restrict__ res,
             float* __restrict__ C, __half* __restrict__ Ch,
             int M, int N, int K, int epi, int ohalf) {
    extern __shared__ uint32_t smu[];
    uint32_t sbase = (uint32_t)__cvta_generic_to_shared(smu);

    int tid = threadIdx.x;
    int bx = blockIdx.x;   // N tile
    int by = blockIdx.y;   // M tile
    int warp = tid >> 5;
    int lane = tid & 31;
    int wm = warp >> 2;    // 0..1 (64 rows)
    int wn = warp & 3;     // 0..3 (32 cols)
    int g  = lane >> 2;    // 0..7
    int tg = lane & 3;     // 0..3

    float acc[4][4][4];
    #pragma unroll
    for (int mi = 0; mi < 4; mi++)
        #pragma unroll
        for (int ni = 0; ni < 4; ni++)
            #pragma unroll
            for (int r = 0; r < 4; r++) acc[mi][ni][r] = 0.f;

    // A copy: row am = tid>>1 (0..127), half-col = (tid&1)*16; 2 x uint4
    int am = tid >> 1;
    const __half* Ag = A + (size_t)(by * 128 + am) * K + (tid & 1) * 16;
    // B copy: k2-row kk = tid>>4 (0..15), n0 = (tid&15)*8; 2 x uint4
    int kk = tid >> 4;
    int n0c = (tid & 15) * 8;
    const uint32_t* Wg = Wh + (size_t)kk * N + bx * 128 + n0c;

    // ldmatrix lane offset (words)
    int sel = lane >> 3;
    int rr  = lane & 7;
    int aLaneOff = ((sel & 1) * 8 + rr) * AP + (sel >> 1) * 4;

    int m0base = wm * 64;
    int n0base = wn * 32;
    int nT = K >> 5;

    uint4 aR0, aR1, bR0, bR1;
    auto ldg = [&](int t) {
        const __half* Asrc = Ag + t * 32;
        aR0 = *(const uint4*)(Asrc);
        aR1 = *(const uint4*)(Asrc + 8);
        const uint32_t* Wsrc = Wg + (size_t)(t * 16) * N;
        bR0 = *(const uint4*)(Wsrc);
        bR1 = *(const uint4*)(Wsrc + 4);
    };
    auto sts = [&](int buf) {
        uint32_t* sA = smu + buf * STW;
        uint32_t* sB = sA + AWORDS;
        int aw = am * AP + (tid & 1) * 8;
        *(uint4*)&sA[aw]     = aR0;
        *(uint4*)&sA[aw + 4] = aR1;
        int bw = kk * BP + n0c;
        *(uint4*)&sB[bw]     = bR0;
        *(uint4*)&sB[bw + 4] = bR1;
    };

    // prologue
    ldg(0);
    sts(0);
    ldg(1);
    __syncthreads();

    for (int t = 0; t < nT; t++) {
        if (t + 1 < nT) sts((t + 1) & 1);
        if (t + 2 < nT) ldg(t + 2);

        uint32_t sA = sbase + (uint32_t)((t & 1) * STW) * 4u;
        const uint32_t* sB = smu + (t & 1) * STW + AWORDS;

        #pragma unroll
        for (int ks = 0; ks < 2; ks++) {        // two k16 steps
            int kw = ks * 8;                    // word (half2) offset
            uint32_t af[4][4];
            #pragma unroll
            for (int mi = 0; mi < 4; mi++)
                ldsm_x4(af[mi], sA + 4u * (uint32_t)((m0base + mi * 16) * AP + kw + aLaneOff));
            uint32_t bf[4][2];
            #pragma unroll
            for (int ni = 0; ni < 4; ni++) {
                int idx = (kw + tg) * BP + n0base + ni * 8 + g;
                bf[ni][0] = sB[idx];
                bf[ni][1] = sB[idx + 4 * BP];
            }
            #pragma unroll
            for (int mi = 0; mi < 4; mi++)
                #pragma unroll
                for (int ni = 0; ni < 4; ni++)
                    mma_f16(acc[mi][ni], af[mi], bf[ni][0], bf[ni][1]);
        }
        __syncthreads();
    }

    // Epilogue. c0:(g, 2tg) c1:(g, 2tg+1) c2:(g+8, 2tg) c3:(g+8, 2tg+1)
    #pragma unroll
    for (int mi = 0; mi < 4; mi++) {
        #pragma unroll
        for (int ni = 0; ni < 4; ni++) {
            int col = bx * 128 + wn * 32 + ni * 8 + tg * 2;
            float b0 = bias[col], b1 = bias[col + 1];
            #pragma unroll
            for (int half = 0; half < 2; half++) {
                int orow = by * 128 + wm * 64 + mi * 16 + g + half * 8;
                size_t off = (size_t)orow * N + col;
                float v0 = acc[mi][ni][half * 2 + 0] + b0;
                float v1 = acc[mi][ni][half * 2 + 1] + b1;
                if (epi == 1) {
                    float u0 = v0 * (0.7978845608028654f + 0.035677408136300125f * v0 * v0);
                    float u1 = v1 * (0.7978845608028654f + 0.035677408136300125f * v1 * v1);
                    v0 = 0.5f * v0 * (1.f + tanhf(u0));
                    v1 = 0.5f * v1 * (1.f + tanhf(u1));
                } else if (epi == 2) {
                    v0 += res[off];
                    v1 += res[off + 1];
                }
                if (ohalf) {
                    *(uint32_t*)(Ch + off) = pack_h2(v0, v1);
                } else {
                    *(float2*)(C + off) = make_float2(v0, v1);
                }
            }
        }
    }
}

// ---------------------------------------------------------------------------
// RMSNorm -> __half output (GEMM A input)
// ---------------------------------------------------------------------------
__global__ void rmsnorm_kernel(const float* __restrict__ x,
                               const float* __restrict__ w,
                               __half* __restrict__ out) {
    int row = blockIdx.x;
    int tid = threadIdx.x;
    const float4* xr = (const float4*)(x + (size_t)row * EE);
    float4 v = xr[tid];
    float ss = v.x*v.x + v.y*v.y + v.z*v.z + v.w*v.w;
    #pragma unroll
    for (int o = 16; o; o >>= 1) ss += __shfl_xor_sync(0xffffffffu, ss, o);
    __shared__ float red[8];
    if ((tid & 31) == 0) red[tid >> 5] = ss;
    __syncthreads();
    float tot = 0.f;
    #pragma unroll
    for (int i = 0; i < 8; i++) tot += red[i];
    float scale = rsqrtf(tot * (1.0f / (float)EE) + 1e-6f);
    float4 wv = ((const float4*)w)[tid];
    uint2 o;
    o.x = pack_h2(v.x * scale * wv.x, v.y * scale * wv.y);
    o.y = pack_h2(v.z * scale * wv.z, v.w * scale * wv.w);
    *(uint2*)(out + (size_t)row * EE + tid * 4) = o;
}

// ---------------------------------------------------------------------------
// Attention pass A: per-chunk state sums.
// ---------------------------------------------------------------------------
__global__ void __launch_bounds__(256)
attn_chunk_state(const float* __restrict__ qkv, float* __restrict__ state) {
    int blk = blockIdx.x;
    int c = blk % NCH;
    int bh = blk / NCH;
    int b = bh / HH, h = bh % HH;

    __shared__ float sk[CHK][DD + 1];
    __shared__ float sv[CHK][DD + 1];
    __shared__ float cw[CHK], sw[CHK];

    int tid = threadIdx.x;
    for (int idx = tid; idx < CHK * 16; idx += 256) {
        int j = idx >> 4;
        int dd = (idx & 15) << 2;
        int l = c * CHK + j;
        const float* base = qkv + (size_t)(b * LL + l) * (3 * EE) + h * DD;
        float4 kv = *(const float4*)(base + EE + dd);
        float4 vv = *(const float4*)(base + 2 * EE + dd);
        sk[j][dd + 0] = fmaxf(kv.x, 0.f);
        sk[j][dd + 1] = fmaxf(kv.y, 0.f);
        sk[j][dd + 2] = fmaxf(kv.z, 0.f);
        sk[j][dd + 3] = fmaxf(kv.w, 0.f);
        sv[j][dd + 0] = vv.x;
        sv[j][dd + 1] = vv.y;
        sv[j][dd + 2] = vv.z;
        sv[j][dd + 3] = vv.w;
    }
    if (tid < CHK) {
        float ang = 1.5707963267948966f * (float)(c * CHK + tid) / (float)LL;
        cw[tid] = cosf(ang);
        sw[tid] = sinf(ang);
    }
    __syncthreads();

    int e  = tid & 63;
    int d0 = (tid >> 6) * 16;
    float accC[16], accS[16];
    #pragma unroll
    for (int r = 0; r < 16; r++) { accC[r] = 0.f; accS[r] = 0.f; }

    for (int j = 0; j < CHK; j++) {
        float ve = sv[j][e];
        float t1 = ve * cw[j];
        float t2 = ve * sw[j];
        #pragma unroll
        for (int r = 0; r < 16; r++) {
            float kd = sk[j][d0 + r];
            accC[r] = fmaf(kd, t1, accC[r]);
            accS[r] = fmaf(kd, t2, accS[r]);
        }
    }

    float* st = state + ((size_t)bh * NCH + c) * ST_STRIDE;
    #pragma unroll
    for (int r = 0; r < 16; r++) {
        st[(d0 + r) * 64 + e]        = accC[r];
        st[4096 + (d0 + r) * 64 + e] = accS[r];
    }
    if (tid < DD) {
        float zc = 0.f, zs = 0.f;
        for (int j = 0; j < CHK; j++) {
            float kd = sk[j][tid];
            zc = fmaf(kd, cw[j], zc);
            zs = fmaf(kd, sw[j], zs);
        }
        st[8192 + tid] = zc;
        st[8256 + tid] = zs;
    }
}

// ---------------------------------------------------------------------------
// Attention pass B: exclusive prefix over chunks (in-place).
// ---------------------------------------------------------------------------
__global__ void attn_prefix(float* __restrict__ state) {
    int bh  = blockIdx.y;
    int idx = blockIdx.x * 256 + threadIdx.x;
    if (idx >= ST_STRIDE) return;
    float* p = state + (size_t)bh * NCH * ST_STRIDE + idx;
    float vals[NCH];
    #pragma unroll
    for (int cc = 0; cc < NCH; cc++) vals[cc] = p[(size_t)cc * ST_STRIDE];
    float run = 0.f;
    #pragma unroll
    for (int cc = 0; cc < NCH; cc++) {
        p[(size_t)cc * ST_STRIDE] = run;
        run += vals[cc];
    }
}

// ---------------------------------------------------------------------------
// Attention pass C: per-chunk output -> __half (out-proj GEMM A input).
// ---------------------------------------------------------------------------
#define ATTN_SMEM_FLOATS (6 * 64 * 65 + 64 + 64 + 64 + 64 + 256 + 64)
#define ATTN_SMEM_BYTES (ATTN_SMEM_FLOATS * 4)

__global__ void __launch_bounds__(256)
attn_out_kernel(const float* __restrict__ qkv, const float* __restrict__ state,
                __half* __restrict__ out) {
    extern __shared__ float smf[];
    float* sq = smf;
    float* sk = sq + 4160;
    float* sv = sk + 4160;
    float* Sc = sv + 4160;
    float* Ss = Sc + 4160;
    float* AS = Ss + 4160;
    float* cw = AS + 4160;
    float* sw = cw + 64;
    float* Zc = sw + 64;
    float* Zs = Zc + 64;
    float* normp = Zs + 64;
    float* normF = normp + 256;

    int blk = blockIdx.x;
    int c = blk % NCH;
    int bh = blk / NCH;
    int b = bh / HH, h = bh % HH;
    int tid = threadIdx.x;

    const float* st = state + ((size_t)bh * NCH + c) * ST_STRIDE;

    for (int idx = tid; idx < CHK * 16; idx += 256) {
        int j = idx >> 4;
        int dd = (idx & 15) << 2;
        int l = c * CHK + j;
        const float* base = qkv + (size_t)(b * LL + l) * (3 * EE) + h * DD;
        float4 qv = *(const float4*)(base + dd);
        float4 kv = *(const float4*)(base + EE + dd);
        float4 vv = *(const float4*)(base + 2 * EE + dd);
        int ro = j * 65 + dd;
        sq[ro + 0] = fmaxf(qv.x, 0.f); sq[ro + 1] = fmaxf(qv.y, 0.f);
        sq[ro + 2] = fmaxf(qv.z, 0.f); sq[ro + 3] = fmaxf(qv.w, 0.f);
        sk[ro + 0] = fmaxf(kv.x, 0.f); sk[ro + 1] = fmaxf(kv.y, 0.f);
        sk[ro + 2] = fmaxf(kv.z, 0.f); sk[ro + 3] = fmaxf(kv.w, 0.f);
        sv[ro + 0] = vv.x; sv[ro + 1] = vv.y; sv[ro + 2] = vv.z; sv[ro + 3] = vv.w;
        int flat = idx << 2;
        int d = flat >> 6, e = flat & 63;
        float4 scv = *(const float4*)(st + flat);
        float4 ssv = *(const float4*)(st + 4096 + flat);
        int so = d * 65 + e;
        Sc[so + 0] = scv.x; Sc[so + 1] = scv.y; Sc[so + 2] = scv.z; Sc[so + 3] = scv.w;
        Ss[so + 0] = ssv.x; Ss[so + 1] = ssv.y; Ss[so + 2] = ssv.z; Ss[so + 3] = ssv.w;
    }
    if (tid < CHK) {
        float ang = 1.5707963267948966f * (float)(c * CHK + tid) / (float)LL;
        cw[tid] = cosf(ang);
        sw[tid] = sinf(ang);
        Zc[tid] = st[8192 + tid];
        Zs[tid] = st[8256 + tid];
    }
    __syncthreads();

    {
        int jc = tid >> 6;
        int i  = tid & 63;
        float acc[16];
        #pragma unroll
        for (int r = 0; r < 16; r++) acc[r] = 0.f;
        for (int d = 0; d < DD; d++) {
            float qv = sq[i * 65 + d];
            #pragma unroll
            for (int r = 0; r < 16; r++)
                acc[r] = fmaf(qv, sk[(jc * 16 + r) * 65 + d], acc[r]);
        }
        float cwi = cw[i], swi = sw[i];
        float rsum = 0.f;
        #pragma unroll
        for (int r = 0; r < 16; r++) {
            int j = jc * 16 + r;
            float wgt = (j <= i) ? (cwi * cw[j] + swi * sw[j]) : 0.f;
            float a = acc[r] * wgt;
            AS[i * 65 + j] = a;
            rsum += a;
        }
        normp[jc * 64 + i] = rsum;
    }
    __syncthreads();

    if (tid < 64) {
        int i = tid;
        float n = normp[i] + normp[64 + i] + normp[128 + i] + normp[192 + i];
        float dc = 0.f, ds = 0.f;
        for (int d = 0; d < DD; d++) {
            float qv = sq[i * 65 + d];
            dc = fmaf(qv, Zc[d], dc);
            ds = fmaf(qv, Zs[d], ds);
        }
        normF[i] = n + cw[i] * dc + sw[i] * ds;
    }

    int ec = tid >> 6;
    int i2 = tid & 63;
    int e0 = ec * 16;
    float accO[16], accC2[16], accS2[16];
    #pragma unroll
    for (int r = 0; r < 16; r++) { accO[r] = 0.f; accC2[r] = 0.f; accS2[r] = 0.f; }

    for (int j = 0; j < CHK; j++) {
        float av = AS[i2 * 65 + j];
        #pragma unroll
        for (int r = 0; r < 16; r++)
            accO[r] = fmaf(av, sv[j * 65 + e0 + r], accO[r]);
    }
    for (int d = 0; d < DD; d++) {
        float qv = sq[i2 * 65 + d];
        #pragma unroll
        for (int r = 0; r < 16; r++) {
            accC2[r] = fmaf(qv, Sc[d * 65 + e0 + r], accC2[r]);
            accS2[r] = fmaf(qv, Ss[d * 65 + e0 + r], accS2[r]);
        }
    }
    __syncthreads();

    float nrm = normF[i2] + 1e-6f;
    float inv = 1.0f / nrm;
    float cwi = cw[i2], swi = sw[i2];
    int lg = c * CHK + i2;
    __half* op = out + (size_t)(b * LL + lg) * EE + h * DD + e0;
    #pragma unroll
    for (int r4 = 0; r4 < 4; r4++) {
        float v0 = (accO[r4*4+0] + cwi*accC2[r4*4+0] + swi*accS2[r4*4+0]) * inv;
        float v1 = (accO[r4*4+1] + cwi*accC2[r4*4+1] + swi*accS2[r4*4+1]) * inv;
        float v2 = (accO[r4*4+2] + cwi*accC2[r4*4+2] + swi*accS2[r4*4+2]) * inv;
        float v3 = (accO[r4*4+3] + cwi*accC2[r4*4+3] + swi*accS2[r4*4+3]) * inv;
        uint2 o;
        o.x = pack_h2(v0, v1);
        o.y = pack_h2(v2, v3);
        *(uint2*)(op + r4 * 4) = o;
    }
}

// ---------------------------------------------------------------------------
// launch
// ---------------------------------------------------------------------------
extern "C" void kernel_launch(void* const* d_in, const int* in_sizes, int n_in,
                              void* d_out, int out_size) {
    const float* x       = (const float*)d_in[0];
    const float* qkv_w   = (const float*)d_in[1];
    const float* qkv_b   = (const float*)d_in[2];
    const float* out_w   = (const float*)d_in[3];
    const float* out_b   = (const float*)d_in[4];
    const float* norm1_w = (const float*)d_in[5];
    const float* norm2_w = (const float*)d_in[6];
    const float* mlp_w1  = (const float*)d_in[7];
    const float* mlp_b1  = (const float*)d_in[8];
    const float* mlp_w2  = (const float*)d_in[9];
    const float* mlp_b2  = (const float*)d_in[10];
    float* out = (float*)d_out;

    float *qkv, *hbuf, *state;
    __half *xnh, *attnh, *midh;
    uint32_t* wh;
    cudaGetSymbolAddress((void**)&qkv, g_qkv);
    cudaGetSymbolAddress((void**)&hbuf, g_h);
    cudaGetSymbolAddress((void**)&state, g_state);
    cudaGetSymbolAddress((void**)&xnh, g_xnh);
    cudaGetSymbolAddress((void**)&attnh, g_attnh);
    cudaGetSymbolAddress((void**)&midh, g_midh);
    cudaGetSymbolAddress((void**)&wh, g_wh);

    cudaFuncSetAttribute(attn_out_kernel,
                         cudaFuncAttributeMaxDynamicSharedMemorySize,
                         ATTN_SMEM_BYTES);
    cudaFuncSetAttribute(tgemm_kernel,
                         cudaFuncAttributeMaxDynamicSharedMemorySize,
                         GEMM_SMEM_BYTES);

    // 0. pack weights to half2 [(k/2)][n]
    wconv_kernel<<<(EE / 2) * (3 * EE / 4) / 256, 256>>>(qkv_w, wh + WOFF_QKV, EE, 3 * EE);
    wconv_kernel<<<(EE / 2) * (EE / 4) / 256, 256>>>(out_w, wh + WOFF_OUT, EE, EE);
    wconv_kernel<<<(EE / 2) * (4 * EE / 4) / 256, 256>>>(mlp_w1, wh + WOFF_W1, EE, 4 * EE);
    wconv_kernel<<<(2 * EE) * (EE / 4) / 256, 256>>>(mlp_w2, wh + WOFF_W2, 4 * EE, EE);

    // 1. xnh = half(rmsnorm(x, norm1_w))
    rmsnorm_kernel<<<ROWS, 256>>>(x, norm1_w, xnh);
    // 2. qkv = xnh @ qkv_w + qkv_b (fp32 out for attention)
    tgemm_kernel<<<dim3(3 * EE / 128, ROWS / 128), 256, GEMM_SMEM_BYTES>>>(
        xnh, wh + WOFF_QKV, qkv_b, nullptr, qkv, nullptr, ROWS, 3 * EE, EE, 0, 0);
    // 3-5. cosformer attention (chunked); attnh emitted as half
    attn_chunk_state<<<BB * HH * NCH, 256>>>(qkv, state);
    attn_prefix<<<dim3((ST_STRIDE + 255) / 256, BB * HH), 256>>>(state);
    attn_out_kernel<<<BB * HH * NCH, 256, ATTN_SMEM_BYTES>>>(qkv, state, attnh);
    // 6. h = attnh @ out_w + out_b + x (fp32)
    tgemm_kernel<<<dim3(EE / 128, ROWS / 128), 256, GEMM_SMEM_BYTES>>>(
        attnh, wh + WOFF_OUT, out_b, x, hbuf, nullptr, ROWS, EE, EE, 2, 0);
    // 7. xnh = half(rmsnorm(h, norm2_w))
    rmsnorm_kernel<<<ROWS, 256>>>(hbuf, norm2_w, xnh);
    // 8. midh = half(gelu(xnh @ mlp_w1 + mlp_b1))
    tgemm_kernel<<<dim3(4 * EE / 128, ROWS / 128), 256, GEMM_SMEM_BYTES>>>(
        xnh, wh + WOFF_W1, mlp_b1, nullptr, nullptr, midh, ROWS, 4 * EE, EE, 1, 1);
    // 9. out = midh @ mlp_w2 + mlp_b2 + h (fp32 final)
    tgemm_kernel<<<dim3(EE / 128, ROWS / 128), 256, GEMM_SMEM_BYTES>>>(
        midh, wh + WOFF_W2, mlp_b2, hbuf, out, nullptr, ROWS, EE, 4 * EE, 2, 0);
}

// round 12
// speedup vs baseline: 2.0480x; 1.0186x over previous
#include <cuda_runtime.h>
#include <cuda_fp16.h>
#include <math.h>
#include <stdint.h>

// Problem constants
#define BB 2
#define LL 1024
#define EE 1024
#define HH 16
#define DD 64
#define NCH 16
#define CHK 64
#define ST_STRIDE 8320
#define ROWS (BB*LL)    // 2048

// GEMM smem (half2 words), double buffered:
//   A [128 rows][AP=20 words], B [16 k2-rows][BP=136 words]
#define AP 20
#define BP 136
#define AWORDS (128 * AP)          // 2560
#define BWORDS (16 * BP)           // 2176
#define STW (AWORDS + BWORDS)      // 4736 words
#define GEMM_SMEM_BYTES (2 * STW * 4)  // 37888

// Scratch (device globals; no allocs allowed)
__device__ float  g_qkv[ROWS * 3 * EE];
__device__ float  g_h[ROWS * EE];
__device__ float  g_state[BB * HH * NCH * ST_STRIDE];
__device__ __half g_xnh[ROWS * EE];
__device__ __half g_attnh[ROWS * EE];
__device__ __half g_midh[ROWS * 4 * EE];
// packed half2 weights: [k/2][n] words; qkv | out | mlp1 | mlp2
#define WOFF_QKV 0
#define WOFF_OUT (WOFF_QKV + (EE/2) * 3 * EE)
#define WOFF_W1  (WOFF_OUT + (EE/2) * EE)
#define WOFF_W2  (WOFF_W1  + (EE/2) * 4 * EE)
#define WTOTAL   (WOFF_W2  + (2 * EE) * EE)
__device__ uint32_t g_wh[WTOTAL];                  // 24 MB

// segment boundaries in uint4 units for merged wconv
#define SEG0 393216    // qkv:  (EE/2)*(3EE/4)
#define SEG1 524288    // +out: (EE/2)*(EE/4)
#define SEG2 1048576   // +w1:  (EE/2)*(4EE/4)
#define SEG3 1572864   // +w2:  (2EE)*(EE/4)

// ---------------------------------------------------------------------------
// helpers
// ---------------------------------------------------------------------------
__device__ __forceinline__ uint32_t pack_h2(float lo, float hi) {
    __half2 h = __floats2half2_rn(lo, hi);
    return *reinterpret_cast<uint32_t*>(&h);
}

__device__ __forceinline__ float gelu_fast(float v) {
    float u = v * (0.7978845608028654f + 0.035677408136300125f * v * v);
    float a = fabsf(u);
    float e = __expf(fminf(2.f * a, 80.f));
    float th = 1.f - __fdividef(2.f, e + 1.f);
    th = copysignf(th, u);
    return 0.5f * v * (1.f + th);
}

__device__ __forceinline__ void mma_f16(float* c, const uint32_t* a,
                                        uint32_t b0, uint32_t b1) {
    asm volatile(
        "mma.sync.aligned.m16n8k16.row.col.f32.f16.f16.f32 "
        "{%0,%1,%2,%3}, {%4,%5,%6,%7}, {%8,%9}, {%0,%1,%2,%3};"
        : "+f"(c[0]), "+f"(c[1]), "+f"(c[2]), "+f"(c[3])
        : "r"(a[0]), "r"(a[1]), "r"(a[2]), "r"(a[3]),
          "r"(b0), "r"(b1));
}

__device__ __forceinline__ void ldsm_x4(uint32_t* d, uint32_t saddr) {
    asm volatile("ldmatrix.sync.aligned.m8n8.x4.shared.b16 {%0,%1,%2,%3}, [%4];"
                 : "=r"(d[0]), "=r"(d[1]), "=r"(d[2]), "=r"(d[3])
                 : "r"(saddr));
}

// ---------------------------------------------------------------------------
// Merged weight convert: all four weights fp32 [K][N] -> packed half2 [(k/2)][n]
// One launch; segment selected by flat uint4 index.
// ---------------------------------------------------------------------------
__global__ void wconv_all(const float* __restrict__ qkv_w,
                          const float* __restrict__ out_w,
                          const float* __restrict__ w1,
                          const float* __restrict__ w2,
                          uint32_t* __restrict__ wh) {
    int idx = blockIdx.x * 256 + threadIdx.x;
    const float* in;
    uint32_t* out;
    int N, li;
    if (idx < SEG0)      { in = qkv_w; out = wh + WOFF_QKV; N = 3 * EE; li = idx; }
    else if (idx < SEG1) { in = out_w; out = wh + WOFF_OUT; N = EE;     li = idx - SEG0; }
    else if (idx < SEG2) { in = w1;    out = wh + WOFF_W1;  N = 4 * EE; li = idx - SEG1; }
    else                 { in = w2;    out = wh + WOFF_W2;  N = EE;     li = idx - SEG2; }
    int nq = N >> 2;
    int r = li / nq;
    int n = (li - r * nq) << 2;
    const float* r0 = in + (size_t)(2 * r) * N + n;
    const float* r1 = r0 + N;
    float4 a = *(const float4*)r0;
    float4 b = *(const float4*)r1;
    uint4 u;
    u.x = pack_h2(a.x, b.x);
    u.y = pack_h2(a.y, b.y);
    u.z = pack_h2(a.z, b.z);
    u.w = pack_h2(a.w, b.w);
    *(uint4*)(out + (size_t)r * N + n) = u;
}

// ---------------------------------------------------------------------------
// FP16 mma.sync GEMM: LDG->reg->STS double buffer, 1 sync/tile, 2 CTAs/SM.
// (unchanged from R11 winner, except gelu_fast in epilogue)
// ---------------------------------------------------------------------------
__global__ void __launch_bounds__(256, 2)
tgemm_kernel(const __half* __restrict__ A, const uint32_t* __restrict__ Wh,
             const float* __restrict__ bias, const float* __restrict__ res,
             float* __restrict__ C, __half* __restrict__ Ch,
             int M, int N, int K, int epi, int ohalf) {
    extern __shared__ uint32_t smu[];
    uint32_t sbase = (uint32_t)__cvta_generic_to_shared(smu);

    int tid = threadIdx.x;
    int bx = blockIdx.x;   // N tile
    int by = blockIdx.y;   // M tile
    int warp = tid >> 5;
    int lane = tid & 31;
    int wm = warp >> 2;    // 0..1 (64 rows)
    int wn = warp & 3;     // 0..3 (32 cols)
    int g  = lane >> 2;    // 0..7
    int tg = lane & 3;     // 0..3

    float acc[4][4][4];
    #pragma unroll
    for (int mi = 0; mi < 4; mi++)
        #pragma unroll
        for (int ni = 0; ni < 4; ni++)
            #pragma unroll
            for (int r = 0; r < 4; r++) acc[mi][ni][r] = 0.f;

    int am = tid >> 1;
    const __half* Ag = A + (size_t)(by * 128 + am) * K + (tid & 1) * 16;
    int kk = tid >> 4;
    int n0c = (tid & 15) * 8;
    const uint32_t* Wg = Wh + (size_t)kk * N + bx * 128 + n0c;

    int sel = lane >> 3;
    int rr  = lane & 7;
    int aLaneOff = ((sel & 1) * 8 + rr) * AP + (sel >> 1) * 4;

    int m0base = wm * 64;
    int n0base = wn * 32;
    int nT = K >> 5;

    uint4 aR0, aR1, bR0, bR1;
    auto ldg = [&](int t) {
        const __half* Asrc = Ag + t * 32;
        aR0 = *(const uint4*)(Asrc);
        aR1 = *(const uint4*)(Asrc + 8);
        const uint32_t* Wsrc = Wg + (size_t)(t * 16) * N;
        bR0 = *(const uint4*)(Wsrc);
        bR1 = *(const uint4*)(Wsrc + 4);
    };
    auto sts = [&](int buf) {
        uint32_t* sA = smu + buf * STW;
        uint32_t* sB = sA + AWORDS;
        int aw = am * AP + (tid & 1) * 8;
        *(uint4*)&sA[aw]     = aR0;
        *(uint4*)&sA[aw + 4] = aR1;
        int bw = kk * BP + n0c;
        *(uint4*)&sB[bw]     = bR0;
        *(uint4*)&sB[bw + 4] = bR1;
    };

    // prologue
    ldg(0);
    sts(0);
    ldg(1);
    __syncthreads();

    for (int t = 0; t < nT; t++) {
        if (t + 1 < nT) sts((t + 1) & 1);
        if (t + 2 < nT) ldg(t + 2);

        uint32_t sA = sbase + (uint32_t)((t & 1) * STW) * 4u;
        const uint32_t* sB = smu + (t & 1) * STW + AWORDS;

        #pragma unroll
        for (int ks = 0; ks < 2; ks++) {
            int kw = ks * 8;
            uint32_t af[4][4];
            #pragma unroll
            for (int mi = 0; mi < 4; mi++)
                ldsm_x4(af[mi], sA + 4u * (uint32_t)((m0base + mi * 16) * AP + kw + aLaneOff));
            uint32_t bf[4][2];
            #pragma unroll
            for (int ni = 0; ni < 4; ni++) {
                int idx = (kw + tg) * BP + n0base + ni * 8 + g;
                bf[ni][0] = sB[idx];
                bf[ni][1] = sB[idx + 4 * BP];
            }
            #pragma unroll
            for (int mi = 0; mi < 4; mi++)
                #pragma unroll
                for (int ni = 0; ni < 4; ni++)
                    mma_f16(acc[mi][ni], af[mi], bf[ni][0], bf[ni][1]);
        }
        __syncthreads();
    }

    // Epilogue
    #pragma unroll
    for (int mi = 0; mi < 4; mi++) {
        #pragma unroll
        for (int ni = 0; ni < 4; ni++) {
            int col = bx * 128 + wn * 32 + ni * 8 + tg * 2;
            float b0 = bias[col], b1 = bias[col + 1];
            #pragma unroll
            for (int half = 0; half < 2; half++) {
                int orow = by * 128 + wm * 64 + mi * 16 + g + half * 8;
                size_t off = (size_t)orow * N + col;
                float v0 = acc[mi][ni][half * 2 + 0] + b0;
                float v1 = acc[mi][ni][half * 2 + 1] + b1;
                if (epi == 1) {
                    v0 = gelu_fast(v0);
                    v1 = gelu_fast(v1);
                } else if (epi == 2) {
                    v0 += res[off];
                    v1 += res[off + 1];
                }
                if (ohalf) {
                    *(uint32_t*)(Ch + off) = pack_h2(v0, v1);
                } else {
                    *(float2*)(C + off) = make_float2(v0, v1);
                }
            }
        }
    }
}

// ---------------------------------------------------------------------------
// RMSNorm -> __half output (GEMM A input)
// ---------------------------------------------------------------------------
__global__ void rmsnorm_kernel(const float* __restrict__ x,
                               const float* __restrict__ w,
                               __half* __restrict__ out) {
    int row = blockIdx.x;
    int tid = threadIdx.x;
    const float4* xr = (const float4*)(x + (size_t)row * EE);
    float4 v = xr[tid];
    float ss = v.x*v.x + v.y*v.y + v.z*v.z + v.w*v.w;
    #pragma unroll
    for (int o = 16; o; o >>= 1) ss += __shfl_xor_sync(0xffffffffu, ss, o);
    __shared__ float red[8];
    if ((tid & 31) == 0) red[tid >> 5] = ss;
    __syncthreads();
    float tot = 0.f;
    #pragma unroll
    for (int i = 0; i < 8; i++) tot += red[i];
    float scale = rsqrtf(tot * (1.0f / (float)EE) + 1e-6f);
    float4 wv = ((const float4*)w)[tid];
    uint2 o;
    o.x = pack_h2(v.x * scale * wv.x, v.y * scale * wv.y);
    o.y = pack_h2(v.z * scale * wv.z, v.w * scale * wv.w);
    *(uint2*)(out + (size_t)row * EE + tid * 4) = o;
}

// ---------------------------------------------------------------------------
// Attention pass A: per-chunk state sums.
// ---------------------------------------------------------------------------
__global__ void __launch_bounds__(256)
attn_chunk_state(const float* __restrict__ qkv, float* __restrict__ state) {
    int blk = blockIdx.x;
    int c = blk % NCH;
    int bh = blk / NCH;
    int b = bh / HH, h = bh % HH;

    __shared__ float sk[CHK][DD + 1];
    __shared__ float sv[CHK][DD + 1];
    __shared__ float cw[CHK], sw[CHK];

    int tid = threadIdx.x;
    for (int idx = tid; idx < CHK * 16; idx += 256) {
        int j = idx >> 4;
        int dd = (idx & 15) << 2;
        int l = c * CHK + j;
        const float* base = qkv + (size_t)(b * LL + l) * (3 * EE) + h * DD;
        float4 kv = *(const float4*)(base + EE + dd);
        float4 vv = *(const float4*)(base + 2 * EE + dd);
        sk[j][dd + 0] = fmaxf(kv.x, 0.f);
        sk[j][dd + 1] = fmaxf(kv.y, 0.f);
        sk[j][dd + 2] = fmaxf(kv.z, 0.f);
        sk[j][dd + 3] = fmaxf(kv.w, 0.f);
        sv[j][dd + 0] = vv.x;
        sv[j][dd + 1] = vv.y;
        sv[j][dd + 2] = vv.z;
        sv[j][dd + 3] = vv.w;
    }
    if (tid < CHK) {
        float ang = 1.5707963267948966f * (float)(c * CHK + tid) / (float)LL;
        cw[tid] = cosf(ang);
        sw[tid] = sinf(ang);
    }
    __syncthreads();

    int e  = tid & 63;
    int d0 = (tid >> 6) * 16;
    float accC[16], accS[16];
    #pragma unroll
    for (int r = 0; r < 16; r++) { accC[r] = 0.f; accS[r] = 0.f; }

    for (int j = 0; j < CHK; j++) {
        float ve = sv[j][e];
        float t1 = ve * cw[j];
        float t2 = ve * sw[j];
        #pragma unroll
        for (int r = 0; r < 16; r++) {
            float kd = sk[j][d0 + r];
            accC[r] = fmaf(kd, t1, accC[r]);
            accS[r] = fmaf(kd, t2, accS[r]);
        }
    }

    float* st = state + ((size_t)bh * NCH + c) * ST_STRIDE;
    #pragma unroll
    for (int r = 0; r < 16; r++) {
        st[(d0 + r) * 64 + e]        = accC[r];
        st[4096 + (d0 + r) * 64 + e] = accS[r];
    }
    if (tid < DD) {
        float zc = 0.f, zs = 0.f;
        for (int j = 0; j < CHK; j++) {
            float kd = sk[j][tid];
            zc = fmaf(kd, cw[j], zc);
            zs = fmaf(kd, sw[j], zs);
        }
        st[8192 + tid] = zc;
        st[8256 + tid] = zs;
    }
}

// ---------------------------------------------------------------------------
// Attention pass B: exclusive prefix over chunks (in-place).
// ---------------------------------------------------------------------------
__global__ void attn_prefix(float* __restrict__ state) {
    int bh  = blockIdx.y;
    int idx = blockIdx.x * 256 + threadIdx.x;
    if (idx >= ST_STRIDE) return;
    float* p = state + (size_t)bh * NCH * ST_STRIDE + idx;
    float vals[NCH];
    #pragma unroll
    for (int cc = 0; cc < NCH; cc++) vals[cc] = p[(size_t)cc * ST_STRIDE];
    float run = 0.f;
    #pragma unroll
    for (int cc = 0; cc < NCH; cc++) {
        p[(size_t)cc * ST_STRIDE] = run;
        run += vals[cc];
    }
}

// ---------------------------------------------------------------------------
// Attention pass C: per-chunk output -> __half (out-proj GEMM A input).
// ---------------------------------------------------------------------------
#define ATTN_SMEM_FLOATS (6 * 64 * 65 + 64 + 64 + 64 + 64 + 256 + 64)
#define ATTN_SMEM_BYTES (ATTN_SMEM_FLOATS * 4)

__global__ void __launch_bounds__(256)
attn_out_kernel(const float* __restrict__ qkv, const float* __restrict__ state,
                __half* __restrict__ out) {
    extern __shared__ float smf[];
    float* sq = smf;
    float* sk = sq + 4160;
    float* sv = sk + 4160;
    float* Sc = sv + 4160;
    float* Ss = Sc + 4160;
    float* AS = Ss + 4160;
    float* cw = AS + 4160;
    float* sw = cw + 64;
    float* Zc = sw + 64;
    float* Zs = Zc + 64;
    float* normp = Zs + 64;
    float* normF = normp + 256;

    int blk = blockIdx.x;
    int c = blk % NCH;
    int bh = blk / NCH;
    int b = bh / HH, h = bh % HH;
    int tid = threadIdx.x;

    const float* st = state + ((size_t)bh * NCH + c) * ST_STRIDE;

    for (int idx = tid; idx < CHK * 16; idx += 256) {
        int j = idx >> 4;
        int dd = (idx & 15) << 2;
        int l = c * CHK + j;
        const float* base = qkv + (size_t)(b * LL + l) * (3 * EE) + h * DD;
        float4 qv = *(const float4*)(base + dd);
        float4 kv = *(const float4*)(base + EE + dd);
        float4 vv = *(const float4*)(base + 2 * EE + dd);
        int ro = j * 65 + dd;
        sq[ro + 0] = fmaxf(qv.x, 0.f); sq[ro + 1] = fmaxf(qv.y, 0.f);
        sq[ro + 2] = fmaxf(qv.z, 0.f); sq[ro + 3] = fmaxf(qv.w, 0.f);
        sk[ro + 0] = fmaxf(kv.x, 0.f); sk[ro + 1] = fmaxf(kv.y, 0.f);
        sk[ro + 2] = fmaxf(kv.z, 0.f); sk[ro + 3] = fmaxf(kv.w, 0.f);
        sv[ro + 0] = vv.x; sv[ro + 1] = vv.y; sv[ro + 2] = vv.z; sv[ro + 3] = vv.w;
        int flat = idx << 2;
        int d = flat >> 6, e = flat & 63;
        float4 scv = *(const float4*)(st + flat);
        float4 ssv = *(const float4*)(st + 4096 + flat);
        int so = d * 65 + e;
        Sc[so + 0] = scv.x; Sc[so + 1] = scv.y; Sc[so + 2] = scv.z; Sc[so + 3] = scv.w;
        Ss[so + 0] = ssv.x; Ss[so + 1] = ssv.y; Ss[so + 2] = ssv.z; Ss[so + 3] = ssv.w;
    }
    if (tid < CHK) {
        float ang = 1.5707963267948966f * (float)(c * CHK + tid) / (float)LL;
        cw[tid] = cosf(ang);
        sw[tid] = sinf(ang);
        Zc[tid] = st[8192 + tid];
        Zs[tid] = st[8256 + tid];
    }
    __syncthreads();

    {
        int jc = tid >> 6;
        int i  = tid & 63;
        float acc[16];
        #pragma unroll
        for (int r = 0; r < 16; r++) acc[r] = 0.f;
        for (int d = 0; d < DD; d++) {
            float qv = sq[i * 65 + d];
            #pragma unroll
            for (int r = 0; r < 16; r++)
                acc[r] = fmaf(qv, sk[(jc * 16 + r) * 65 + d], acc[r]);
        }
        float cwi = cw[i], swi = sw[i];
        float rsum = 0.f;
        #pragma unroll
        for (int r = 0; r < 16; r++) {
            int j = jc * 16 + r;
            float wgt = (j <= i) ? (cwi * cw[j] + swi * sw[j]) : 0.f;
            float a = acc[r] * wgt;
            AS[i * 65 + j] = a;
            rsum += a;
        }
        normp[jc * 64 + i] = rsum;
    }
    __syncthreads();

    if (tid < 64) {
        int i = tid;
        float n = normp[i] + normp[64 + i] + normp[128 + i] + normp[192 + i];
        float dc = 0.f, ds = 0.f;
        for (int d = 0; d < DD; d++) {
            float qv = sq[i * 65 + d];
            dc = fmaf(qv, Zc[d], dc);
            ds = fmaf(qv, Zs[d], ds);
        }
        normF[i] = n + cw[i] * dc + sw[i] * ds;
    }

    int ec = tid >> 6;
    int i2 = tid & 63;
    int e0 = ec * 16;
    float accO[16], accC2[16], accS2[16];
    #pragma unroll
    for (int r = 0; r < 16; r++) { accO[r] = 0.f; accC2[r] = 0.f; accS2[r] = 0.f; }

    for (int j = 0; j < CHK; j++) {
        float av = AS[i2 * 65 + j];
        #pragma unroll
        for (int r = 0; r < 16; r++)
            accO[r] = fmaf(av, sv[j * 65 + e0 + r], accO[r]);
    }
    for (int d = 0; d < DD; d++) {
        float qv = sq[i2 * 65 + d];
        #pragma unroll
        for (int r = 0; r < 16; r++) {
            accC2[r] = fmaf(qv, Sc[d * 65 + e0 + r], accC2[r]);
            accS2[r] = fmaf(qv, Ss[d * 65 + e0 + r], accS2[r]);
        }
    }
    __syncthreads();

    float nrm = normF[i2] + 1e-6f;
    float inv = 1.0f / nrm;
    float cwi = cw[i2], swi = sw[i2];
    int lg = c * CHK + i2;
    __half* op = out + (size_t)(b * LL + lg) * EE + h * DD + e0;
    #pragma unroll
    for (int r4 = 0; r4 < 4; r4++) {
        float v0 = (accO[r4*4+0] + cwi*accC2[r4*4+0] + swi*accS2[r4*4+0]) * inv;
        float v1 = (accO[r4*4+1] + cwi*accC2[r4*4+1] + swi*accS2[r4*4+1]) * inv;
        float v2 = (accO[r4*4+2] + cwi*accC2[r4*4+2] + swi*accS2[r4*4+2]) * inv;
        float v3 = (accO[r4*4+3] + cwi*accC2[r4*4+3] + swi*accS2[r4*4+3]) * inv;
        uint2 o;
        o.x = pack_h2(v0, v1);
        o.y = pack_h2(v2, v3);
        *(uint2*)(op + r4 * 4) = o;
    }
}

// ---------------------------------------------------------------------------
// launch
// ---------------------------------------------------------------------------
extern "C" void kernel_launch(void* const* d_in, const int* in_sizes, int n_in,
                              void* d_out, int out_size) {
    const float* x       = (const float*)d_in[0];
    const float* qkv_w   = (const float*)d_in[1];
    const float* qkv_b   = (const float*)d_in[2];
    const float* out_w   = (const float*)d_in[3];
    const float* out_b   = (const float*)d_in[4];
    const float* norm1_w = (const float*)d_in[5];
    const float* norm2_w = (const float*)d_in[6];
    const float* mlp_w1  = (const float*)d_in[7];
    const float* mlp_b1  = (const float*)d_in[8];
    const float* mlp_w2  = (const float*)d_in[9];
    const float* mlp_b2  = (const float*)d_in[10];
    float* out = (float*)d_out;

    float *qkv, *hbuf, *state;
    __half *xnh, *attnh, *midh;
    uint32_t* wh;
    cudaGetSymbolAddress((void**)&qkv, g_qkv);
    cudaGetSymbolAddress((void**)&hbuf, g_h);
    cudaGetSymbolAddress((void**)&state, g_state);
    cudaGetSymbolAddress((void**)&xnh, g_xnh);
    cudaGetSymbolAddress((void**)&attnh, g_attnh);
    cudaGetSymbolAddress((void**)&midh, g_midh);
    cudaGetSymbolAddress((void**)&wh, g_wh);

    cudaFuncSetAttribute(attn_out_kernel,
                         cudaFuncAttributeMaxDynamicSharedMemorySize,
                         ATTN_SMEM_BYTES);
    cudaFuncSetAttribute(tgemm_kernel,
                         cudaFuncAttributeMaxDynamicSharedMemorySize,
                         GEMM_SMEM_BYTES);

    // 0. pack all weights to half2 [(k/2)][n] in ONE launch
    wconv_all<<<SEG3 / 256, 256>>>(qkv_w, out_w, mlp_w1, mlp_w2, wh);

    // 1. xnh = half(rmsnorm(x, norm1_w))
    rmsnorm_kernel<<<ROWS, 256>>>(x, norm1_w, xnh);
    // 2. qkv = xnh @ qkv_w + qkv_b (fp32 out for attention)
    tgemm_kernel<<<dim3(3 * EE / 128, ROWS / 128), 256, GEMM_SMEM_BYTES>>>(
        xnh, wh + WOFF_QKV, qkv_b, nullptr, qkv, nullptr, ROWS, 3 * EE, EE, 0, 0);
    // 3-5. cosformer attention (chunked); attnh emitted as half
    attn_chunk_state<<<BB * HH * NCH, 256>>>(qkv, state);
    attn_prefix<<<dim3((ST_STRIDE + 255) / 256, BB * HH), 256>>>(state);
    attn_out_kernel<<<BB * HH * NCH, 256, ATTN_SMEM_BYTES>>>(qkv, state, attnh);
    // 6. h = attnh @ out_w + out_b + x (fp32)
    tgemm_kernel<<<dim3(EE / 128, ROWS / 128), 256, GEMM_SMEM_BYTES>>>(
        attnh, wh + WOFF_OUT, out_b, x, hbuf, nullptr, ROWS, EE, EE, 2, 0);
    // 7. xnh = half(rmsnorm(h, norm2_w))
    rmsnorm_kernel<<<ROWS, 256>>>(hbuf, norm2_w, xnh);
    // 8. midh = half(gelu(xnh @ mlp_w1 + mlp_b1)) with fast tanh
    tgemm_kernel<<<dim3(4 * EE / 128, ROWS / 128), 256, GEMM_SMEM_BYTES>>>(
        xnh, wh + WOFF_W1, mlp_b1, nullptr, nullptr, midh, ROWS, 4 * EE, EE, 1, 1);
    // 9. out = midh @ mlp_w2 + mlp_b2 + h (fp32 final)
    tgemm_kernel<<<dim3(EE / 128, ROWS / 128), 256, GEMM_SMEM_BYTES>>>(
        midh, wh + WOFF_W2, mlp_b2, hbuf, out, nullptr, ROWS, EE, 4 * EE, 2, 0);
}